// round 3
// baseline (speedup 1.0000x reference)
#include <cuda_runtime.h>
#include <cstddef>

#define B_   8
#define T_   1024
#define C_   768
#define H_   12
#define D_   64
#define M_   (B_ * T_)     /* 8192 */
#define N1_  (3 * C_)      /* 2304 */
#define SCALE_ 0.125f      /* 1/sqrt(64) */

// Scratch (device-global; allocation-free per harness rules)
__device__ float g_q[(size_t)B_ * H_ * T_ * D_];
__device__ float g_k[(size_t)B_ * H_ * T_ * D_];
__device__ float g_v[(size_t)B_ * H_ * T_ * D_];
__device__ float g_ctx[(size_t)M_ * C_];

// ---------------------------------------------------------------------------
// Tiled SGEMM: out[M,N] = A[M,K] @ W[K,N] + bias[N]
// 128x128 tile, BK=8, 256 threads, 8x8 accum per thread.
// MODE 0: A = hidden, N=2304; epilogue scatters into g_q/g_k/g_v [B,H,T,D]
// MODE 1: A = g_ctx,  N=768;  epilogue writes row-major to `out`
// ---------------------------------------------------------------------------
template <int MODE>
__global__ __launch_bounds__(256) void gemm_kernel(
    const float* __restrict__ A_in, const float* __restrict__ W,
    const float* __restrict__ bias, float* __restrict__ out,
    int N, int K)
{
    __shared__ float As[8][128];   // [k][row]  (A transposed)
    __shared__ float Bs[8][128];   // [k][col]

    const float* A = (MODE == 1) ? g_ctx : A_in;

    const int tid = threadIdx.x;
    const int tr = tid >> 4;          // 0..15
    const int tc = tid & 15;          // 0..15
    const int bm = blockIdx.y;
    const int bn = blockIdx.x;

    float acc[8][8];
#pragma unroll
    for (int i = 0; i < 8; i++)
#pragma unroll
        for (int j = 0; j < 8; j++) acc[i][j] = 0.f;

    const int arow = tid >> 1;            // 0..127
    const int acg  = (tid & 1) * 4;       // 0 or 4
    const float* Aptr = A + (size_t)(bm * 128 + arow) * K + acg;

    const int brow = tid >> 5;            // 0..7
    const int bcol = (tid & 31) * 4;      // 0..124
    const float* Wptr = W + (size_t)brow * N + bn * 128 + bcol;

    for (int k0 = 0; k0 < K; k0 += 8) {
        float4 av = *(const float4*)(Aptr + k0);
        As[acg + 0][arow] = av.x;
        As[acg + 1][arow] = av.y;
        As[acg + 2][arow] = av.z;
        As[acg + 3][arow] = av.w;
        float4 bv = *(const float4*)(Wptr + (size_t)k0 * N);
        *(float4*)&Bs[brow][bcol] = bv;
        __syncthreads();

#pragma unroll
        for (int k = 0; k < 8; k++) {
            float4 a0 = *(const float4*)&As[k][tr * 8];
            float4 a1 = *(const float4*)&As[k][tr * 8 + 4];
            float4 b0 = *(const float4*)&Bs[k][tc * 8];
            float4 b1 = *(const float4*)&Bs[k][tc * 8 + 4];
            float ra[8] = {a0.x, a0.y, a0.z, a0.w, a1.x, a1.y, a1.z, a1.w};
            float rb[8] = {b0.x, b0.y, b0.z, b0.w, b1.x, b1.y, b1.z, b1.w};
#pragma unroll
            for (int i = 0; i < 8; i++)
#pragma unroll
                for (int j = 0; j < 8; j++)
                    acc[i][j] += ra[i] * rb[j];
        }
        __syncthreads();
    }

    const int gr0 = bm * 128 + tr * 8;
    const int gc0 = bn * 128 + tc * 8;

    if (MODE == 0) {
        // Scatter QKV into [B,H,T,D] with bias
#pragma unroll
        for (int i = 0; i < 8; i++) {
            int gr = gr0 + i;
            int b  = gr >> 10;
            int t  = gr & 1023;
#pragma unroll
            for (int j = 0; j < 8; j++) {
                int gc = gc0 + j;
                float v = acc[i][j] + bias[gc];
                int which = gc / C_;
                int rem   = gc - which * C_;
                int h = rem >> 6;
                int d = rem & 63;
                size_t idx = (((size_t)(b * H_ + h) * T_ + t) << 6) + d;
                float* dst = (which == 0) ? g_q : (which == 1) ? g_k : g_v;
                dst[idx] = v;
            }
        }
    } else {
#pragma unroll
        for (int i = 0; i < 8; i++) {
            size_t rowoff = (size_t)(gr0 + i) * N + gc0;
#pragma unroll
            for (int j4 = 0; j4 < 8; j4 += 4) {
                float4 o;
                o.x = acc[i][j4 + 0] + bias[gc0 + j4 + 0];
                o.y = acc[i][j4 + 1] + bias[gc0 + j4 + 1];
                o.z = acc[i][j4 + 2] + bias[gc0 + j4 + 2];
                o.w = acc[i][j4 + 3] + bias[gc0 + j4 + 3];
                *(float4*)&out[rowoff + j4] = o;
            }
        }
    }
}

// ---------------------------------------------------------------------------
// Flash-attention (fp32, online softmax).
// Grid: (T/64, B*H). Block: 256 threads = 16x16; each thread owns 4 rows x 4
// cols of S and 4 rows x 4 dims of O. K buffer reused for the P tile.
// ---------------------------------------------------------------------------
#define ATS 68   // smem row stride (floats); 68*4 % 16 == 0 keeps float4 aligned

__global__ __launch_bounds__(256) void attn_kernel()
{
    extern __shared__ float smem[];
    float* Qs = smem;                 // [d][r]   d-major, Q pre-scaled
    float* Ks = smem + 64 * ATS;      // [d][c];  reused as P[r][k]
    float* Vs = smem + 2 * 64 * ATS;  // [k][dim]

    const int tid = threadIdx.x;
    const int ty = tid >> 4;          // 0..15 -> rows 4*ty..
    const int tx = tid & 15;          // 0..15 -> cols/dims 4*tx..
    const int bh = blockIdx.y;
    const int q0 = blockIdx.x * 64;

    const float* Qg = g_q + (size_t)bh * T_ * D_;
    const float* Kg = g_k + (size_t)bh * T_ * D_;
    const float* Vg = g_v + (size_t)bh * T_ * D_;

    // Load Q tile transposed, pre-scaled by 1/sqrt(D).
    // 64x64 tile = 1024 float4s; 256 threads x 4 iterations.
#pragma unroll
    for (int it = 0; it < 4; it++) {
        int idx = it * 256 + tid;
        int r   = idx >> 4;           // 0..63
        int c4  = (idx & 15) * 4;     // 0..60
        float4 v = *(const float4*)(Qg + (size_t)(q0 + r) * D_ + c4);
        Qs[(c4 + 0) * ATS + r] = v.x * SCALE_;
        Qs[(c4 + 1) * ATS + r] = v.y * SCALE_;
        Qs[(c4 + 2) * ATS + r] = v.z * SCALE_;
        Qs[(c4 + 3) * ATS + r] = v.w * SCALE_;
    }

    float m[4], l[4], acc[4][4];
#pragma unroll
    for (int i = 0; i < 4; i++) {
        m[i] = -1e30f;
        l[i] = 0.f;
#pragma unroll
        for (int j = 0; j < 4; j++) acc[i][j] = 0.f;
    }

    for (int kt = 0; kt < T_ / 64; kt++) {
        __syncthreads();   // protect K/V/P from previous iteration's readers
#pragma unroll
        for (int it = 0; it < 4; it++) {
            int idx = it * 256 + tid;
            int r   = idx >> 4;           // 0..63
            int c4  = (idx & 15) * 4;     // 0..60
            float4 kv = *(const float4*)(Kg + (size_t)(kt * 64 + r) * D_ + c4);
            Ks[(c4 + 0) * ATS + r] = kv.x;
            Ks[(c4 + 1) * ATS + r] = kv.y;
            Ks[(c4 + 2) * ATS + r] = kv.z;
            Ks[(c4 + 3) * ATS + r] = kv.w;
            float4 vv = *(const float4*)(Vg + (size_t)(kt * 64 + r) * D_ + c4);
            *(float4*)&Vs[r * ATS + c4] = vv;
        }
        __syncthreads();

        // S tile: s[i][j] = (Q*scale) . K  over d=0..63
        float s[4][4];
#pragma unroll
        for (int i = 0; i < 4; i++)
#pragma unroll
            for (int j = 0; j < 4; j++) s[i][j] = 0.f;

#pragma unroll 8
        for (int d = 0; d < 64; d++) {
            float4 qa = *(const float4*)&Qs[d * ATS + ty * 4];
            float4 kb = *(const float4*)&Ks[d * ATS + tx * 4];
            float ra[4] = {qa.x, qa.y, qa.z, qa.w};
            float rb[4] = {kb.x, kb.y, kb.z, kb.w};
#pragma unroll
            for (int i = 0; i < 4; i++)
#pragma unroll
                for (int j = 0; j < 4; j++)
                    s[i][j] += ra[i] * rb[j];
        }
        __syncthreads();   // all threads done reading Ks before P overwrites it

        // Online softmax + write P (into Ks buffer, layout P[r][k])
#pragma unroll
        for (int i = 0; i < 4; i++) {
            float tm = fmaxf(fmaxf(s[i][0], s[i][1]), fmaxf(s[i][2], s[i][3]));
#pragma unroll
            for (int off = 8; off; off >>= 1)
                tm = fmaxf(tm, __shfl_xor_sync(0xffffffffu, tm, off));
            float mn = fmaxf(m[i], tm);
            float f  = __expf(m[i] - mn);
            m[i] = mn;
            float rs = 0.f;
#pragma unroll
            for (int j = 0; j < 4; j++) {
                float p = __expf(s[i][j] - mn);
                s[i][j] = p;
                rs += p;
            }
#pragma unroll
            for (int off = 8; off; off >>= 1)
                rs += __shfl_xor_sync(0xffffffffu, rs, off);
            l[i] = l[i] * f + rs;
#pragma unroll
            for (int j = 0; j < 4; j++) acc[i][j] *= f;
            *(float4*)&Ks[(ty * 4 + i) * ATS + tx * 4] =
                make_float4(s[i][0], s[i][1], s[i][2], s[i][3]);
        }
        __syncthreads();

        // O += P @ V
#pragma unroll 4
        for (int k4 = 0; k4 < 64; k4 += 4) {
            float Pv[4][4];
            float Vv[4][4];
#pragma unroll
            for (int i = 0; i < 4; i++)
                *(float4*)Pv[i] = *(const float4*)&Ks[(ty * 4 + i) * ATS + k4];
#pragma unroll
            for (int kk = 0; kk < 4; kk++)
                *(float4*)Vv[kk] = *(const float4*)&Vs[(k4 + kk) * ATS + tx * 4];
#pragma unroll
            for (int kk = 0; kk < 4; kk++)
#pragma unroll
                for (int i = 0; i < 4; i++)
#pragma unroll
                    for (int j = 0; j < 4; j++)
                        acc[i][j] += Pv[i][kk] * Vv[kk][j];
        }
    }

    // Normalize and write ctx in [B, T, H*D] layout
    const int b = bh / H_;
    const int h = bh - b * H_;
#pragma unroll
    for (int i = 0; i < 4; i++) {
        float inv = 1.f / l[i];
        int t = q0 + ty * 4 + i;
        float4 o = make_float4(acc[i][0] * inv, acc[i][1] * inv,
                               acc[i][2] * inv, acc[i][3] * inv);
        *(float4*)&g_ctx[(size_t)(b * T_ + t) * C_ + h * D_ + tx * 4] = o;
    }
}

// ---------------------------------------------------------------------------
extern "C" void kernel_launch(void* const* d_in, const int* in_sizes, int n_in,
                              void* d_out, int out_size)
{
    const float* hidden = (const float*)d_in[0];
    const float* qkv_w  = (const float*)d_in[1];
    const float* qkv_b  = (const float*)d_in[2];
    const float* proj_w = (const float*)d_in[3];
    const float* proj_b = (const float*)d_in[4];
    float* out = (float*)d_out;

    (void)in_sizes; (void)n_in; (void)out_size;

    // 1) QKV projection + scatter to [B,H,T,D]
    dim3 g1(N1_ / 128, M_ / 128);
    gemm_kernel<0><<<g1, 256>>>(hidden, qkv_w, qkv_b, nullptr, N1_, C_);

    // 2) Attention (dynamic smem: 3 * 64 * 68 * 4 = 52224 B)
    const int attn_smem = 3 * 64 * ATS * (int)sizeof(float);
    cudaFuncSetAttribute(attn_kernel,
                         cudaFuncAttributeMaxDynamicSharedMemorySize, attn_smem);
    attn_kernel<<<dim3(T_ / 64, B_ * H_), 256, attn_smem>>>();

    // 3) Output projection
    dim3 g2(C_ / 128, M_ / 128);
    gemm_kernel<1><<<g2, 256>>>(nullptr, proj_w, proj_b, out, C_, C_);
}

// round 6
// speedup vs baseline: 1.4155x; 1.4155x over previous
#include <cuda_runtime.h>
#include <cuda_bf16.h>
#include <cstdint>
#include <cstddef>

#define B_   8
#define T_   1024
#define C_   768
#define H_   12
#define D_   64
#define M_   (B_ * T_)     /* 8192 */
#define N1_  (3 * C_)      /* 2304 */
#define SCALE_ 0.125f

// ---------------- device-global scratch (no runtime alloc allowed) ----------
__device__ float g_q[(size_t)M_ * C_];
__device__ float g_k[(size_t)M_ * C_];
__device__ float g_v[(size_t)M_ * C_];
__device__ float g_ctx[(size_t)M_ * C_];

__device__ __nv_bfloat16 g_ahi[(size_t)M_ * C_];
__device__ __nv_bfloat16 g_alo[(size_t)M_ * C_];
__device__ __nv_bfloat16 g_chi[(size_t)M_ * C_];
__device__ __nv_bfloat16 g_clo[(size_t)M_ * C_];
__device__ __nv_bfloat16 g_wq_hi[(size_t)N1_ * C_];  // qkv_w^T  [2304, 768]
__device__ __nv_bfloat16 g_wq_lo[(size_t)N1_ * C_];
__device__ __nv_bfloat16 g_wp_hi[(size_t)C_ * C_];   // proj_w^T [768, 768]
__device__ __nv_bfloat16 g_wp_lo[(size_t)C_ * C_];

// ---------------- PTX helpers ----------------------------------------------
__device__ __forceinline__ uint32_t smem_u32(const void* p) {
    uint32_t a;
    asm("{ .reg .u64 t; cvta.to.shared.u64 t, %1; cvt.u32.u64 %0, t; }"
        : "=r"(a) : "l"(p));
    return a;
}

#define CP_ASYNC16(dst, src) \
    asm volatile("cp.async.cg.shared.global [%0], [%1], 16;" \
                 :: "r"(dst), "l"(src) : "memory")
#define CP_COMMIT() asm volatile("cp.async.commit_group;" ::: "memory")
#define CP_WAIT(n)  asm volatile("cp.async.wait_group %0;" :: "n"(n) : "memory")

__device__ __forceinline__ void ldsm4(uint32_t* r, uint32_t a) {
    asm volatile("ldmatrix.sync.aligned.m8n8.x4.shared.b16 {%0,%1,%2,%3}, [%4];"
                 : "=r"(r[0]), "=r"(r[1]), "=r"(r[2]), "=r"(r[3]) : "r"(a));
}

__device__ __forceinline__ void mma_bf16(float* c, const uint32_t* a,
                                         uint32_t b0, uint32_t b1) {
    asm volatile(
        "mma.sync.aligned.m16n8k16.row.col.f32.bf16.bf16.f32 "
        "{%0,%1,%2,%3}, {%4,%5,%6,%7}, {%8,%9}, {%0,%1,%2,%3};"
        : "+f"(c[0]), "+f"(c[1]), "+f"(c[2]), "+f"(c[3])
        : "r"(a[0]), "r"(a[1]), "r"(a[2]), "r"(a[3]), "r"(b0), "r"(b1));
}

// ---------------- conversion kernels ----------------------------------------
// sel 0: src = external hidden ptr -> g_ahi/g_alo
// sel 1: src = g_ctx (device-internal) -> g_chi/g_clo
__global__ void conv_split_kernel(const float* __restrict__ src_ext, int sel, int n)
{
    int i = blockIdx.x * blockDim.x + threadIdx.x;
    if (i >= n) return;
    const float* src = sel ? g_ctx : src_ext;   // device-side symbol access only
    float x = src[i];
    __nv_bfloat16 h = __float2bfloat16(x);
    __nv_bfloat16 l = __float2bfloat16(x - __bfloat162float(h));
    if (sel == 0) { g_ahi[i] = h; g_alo[i] = l; }
    else          { g_chi[i] = h; g_clo[i] = l; }
}

// W [K, N] fp32 -> W^T [N, K] bf16 hi/lo. dst_sel: 0 = qkv_w, 1 = proj_w
__global__ void conv_transpose_kernel(const float* __restrict__ src, int dst_sel,
                                      int K, int N)
{
    __shared__ float tile[32][33];
    int kx = blockIdx.y * 32;
    int nx = blockIdx.x * 32;
    int tx = threadIdx.x;
    int ty = threadIdx.y;
    for (int i = ty; i < 32; i += 8)
        tile[i][tx] = src[(size_t)(kx + i) * N + nx + tx];
    __syncthreads();
    __nv_bfloat16* dhi = dst_sel ? g_wp_hi : g_wq_hi;
    __nv_bfloat16* dlo = dst_sel ? g_wp_lo : g_wq_lo;
    for (int i = ty; i < 32; i += 8) {
        float v = tile[tx][i];
        __nv_bfloat16 h = __float2bfloat16(v);
        __nv_bfloat16 l = __float2bfloat16(v - __bfloat162float(h));
        size_t o = (size_t)(nx + i) * K + kx + tx;
        dhi[o] = h;
        dlo[o] = l;
    }
}

// ---------------- mma.sync bf16x3 GEMM --------------------------------------
// C[M,N] = A[M,768] @ W[768,N] + bias.  BM=128, BN=128, BK=32 bf16.
// 8 warps: warp_m = wid&3 (32 rows), warp_n = wid>>2 (64 cols).
// smem stage: 4 tiles (Ahi, Alo, Bhi, Blo), each 128 rows x 80B (32 bf16 + pad).
#define BKE 32                       /* K elems per stage */
#define KSB 80                       /* smem row stride bytes */
#define TILE_B (128 * KSB)           /* 10240 */
#define STAGE_B (4 * TILE_B)         /* 40960 */
#define GEMM_SMEM (2 * STAGE_B)      /* 81920 */
#define NKT 24                       /* 768 / 32 */

template <int MODE>
__global__ __launch_bounds__(256, 1)
void gemm_mma_kernel(const float* __restrict__ bias, float* __restrict__ out)
{
    extern __shared__ char smem[];
    const uint32_t sbase = smem_u32(smem);
    const int tid = threadIdx.x;
    const int wid = tid >> 5;
    const int l   = tid & 31;
    const int gm0 = blockIdx.y * 128;
    const int gn0 = blockIdx.x * 128;

    const __nv_bfloat16* gAhi = MODE ? g_chi : g_ahi;
    const __nv_bfloat16* gAlo = MODE ? g_clo : g_alo;
    const __nv_bfloat16* gBhi = MODE ? g_wp_hi : g_wq_hi;
    const __nv_bfloat16* gBlo = MODE ? g_wp_lo : g_wq_lo;

    const int m0 = (wid & 3) * 32;     // warp row offset in tile
    const int n0 = (wid >> 2) * 64;    // warp col offset in tile

    // ldmatrix lane addressing (byte offsets within a tile)
    const int lq = l >> 3, lr = l & 7;
    const uint32_t a_off = (uint32_t)((m0 + (lq & 1) * 8 + lr) * KSB + ((lq >> 1) * 8) * 2);
    const uint32_t b_off = (uint32_t)((n0 + (lq >> 1) * 8 + lr) * KSB + ((lq & 1) * 8) * 2);

    float acc[2][8][4];
#pragma unroll
    for (int mt = 0; mt < 2; mt++)
#pragma unroll
        for (int nt = 0; nt < 8; nt++)
#pragma unroll
            for (int j = 0; j < 4; j++) acc[mt][nt][j] = 0.f;

    // stage loader: 4 tiles x 512 16B-chunks, cp.async
    auto issue_stage = [&](int kt, int s) {
        const int k0 = kt * BKE;
        const uint32_t sb = sbase + (uint32_t)s * STAGE_B;
#pragma unroll
        for (int tile = 0; tile < 4; tile++) {
            const __nv_bfloat16* src =
                (tile == 0) ? gAhi : (tile == 1) ? gAlo : (tile == 2) ? gBhi : gBlo;
            const int g0 = (tile < 2) ? gm0 : gn0;
#pragma unroll
            for (int hf = 0; hf < 2; hf++) {
                int c   = hf * 256 + tid;       // 0..511
                int row = c >> 2;
                int ch  = c & 3;
                const void* gp = src + (size_t)(g0 + row) * C_ + k0 + ch * 8;
                uint32_t dp = sb + (uint32_t)tile * TILE_B + row * KSB + ch * 16;
                CP_ASYNC16(dp, gp);
            }
        }
    };

    issue_stage(0, 0);
    CP_COMMIT();

    for (int kt = 0; kt < NKT; kt++) {
        const int s = kt & 1;
        if (kt + 1 < NKT) {
            issue_stage(kt + 1, s ^ 1);
            CP_COMMIT();
            CP_WAIT(1);
        } else {
            CP_WAIT(0);
        }
        __syncthreads();

        const uint32_t sb = sbase + (uint32_t)s * STAGE_B;
        const uint32_t aHi = sb + a_off;
        const uint32_t aLo = sb + TILE_B + a_off;
        const uint32_t bHi = sb + 2 * TILE_B + b_off;
        const uint32_t bLo = sb + 3 * TILE_B + b_off;

#pragma unroll
        for (int kk = 0; kk < 2; kk++) {
            const uint32_t ko = kk * 32;    // 16 bf16 = 32B
            uint32_t ah[2][4], al[2][4], bh[4][4], bl[4][4];
#pragma unroll
            for (int mt = 0; mt < 2; mt++) {
                ldsm4(ah[mt], aHi + mt * (16 * KSB) + ko);
                ldsm4(al[mt], aLo + mt * (16 * KSB) + ko);
            }
#pragma unroll
            for (int p = 0; p < 4; p++) {
                ldsm4(bh[p], bHi + p * (16 * KSB) + ko);
                ldsm4(bl[p], bLo + p * (16 * KSB) + ko);
            }
#pragma unroll
            for (int mt = 0; mt < 2; mt++)
#pragma unroll
                for (int nt = 0; nt < 8; nt++) {
                    const int p = nt >> 1, o = (nt & 1) * 2;
                    mma_bf16(acc[mt][nt], ah[mt], bh[p][o], bh[p][o + 1]);
                    mma_bf16(acc[mt][nt], ah[mt], bl[p][o], bl[p][o + 1]);
                    mma_bf16(acc[mt][nt], al[mt], bh[p][o], bh[p][o + 1]);
                }
        }
        __syncthreads();
    }

    // ---------------- epilogue ----------------------------------------------
    const int gr_base = gm0 + m0 + (l >> 2);
    const int gc_loc  = 2 * (l & 3);

    if (MODE == 0) {
        const int which    = gn0 / C_;
        const int rem_base = gn0 - which * C_;
        float* dst = (which == 0) ? g_q : (which == 1) ? g_k : g_v;
#pragma unroll
        for (int mt = 0; mt < 2; mt++)
#pragma unroll
            for (int nt = 0; nt < 8; nt++) {
                const float* c = acc[mt][nt];
                const int gcn = n0 + nt * 8 + gc_loc;
                const int gc  = gn0 + gcn;
                float2 bb = *(const float2*)&bias[gc];
                const int rem = rem_base + gcn;
                const int h = rem >> 6, d = rem & 63;
#pragma unroll
                for (int hf = 0; hf < 2; hf++) {
                    const int gr = gr_base + mt * 16 + hf * 8;
                    const int b  = gr >> 10, tq = gr & 1023;
                    float2 o;
                    o.x = c[hf * 2 + 0] + bb.x;
                    o.y = c[hf * 2 + 1] + bb.y;
                    *(float2*)&dst[(((size_t)(b * H_ + h)) * T_ + tq) * D_ + d] = o;
                }
            }
    } else {
#pragma unroll
        for (int mt = 0; mt < 2; mt++)
#pragma unroll
            for (int nt = 0; nt < 8; nt++) {
                const float* c = acc[mt][nt];
                const int gc = gn0 + n0 + nt * 8 + gc_loc;
                float2 bb = *(const float2*)&bias[gc];
#pragma unroll
                for (int hf = 0; hf < 2; hf++) {
                    const int gr = gr_base + mt * 16 + hf * 8;
                    float2 o;
                    o.x = c[hf * 2 + 0] + bb.x;
                    o.y = c[hf * 2 + 1] + bb.y;
                    *(float2*)&out[(size_t)gr * C_ + gc] = o;
                }
            }
    }
}

// ---------------- flash attention (fp32, unchanged from R3) -----------------
#define ATS 68

__global__ __launch_bounds__(256) void attn_kernel()
{
    extern __shared__ float fsm[];
    float* Qs = fsm;
    float* Ks = fsm + 64 * ATS;
    float* Vs = fsm + 2 * 64 * ATS;

    const int tid = threadIdx.x;
    const int ty = tid >> 4;
    const int tx = tid & 15;
    const int bh = blockIdx.y;
    const int q0 = blockIdx.x * 64;

    const float* Qg = g_q + (size_t)bh * T_ * D_;
    const float* Kg = g_k + (size_t)bh * T_ * D_;
    const float* Vg = g_v + (size_t)bh * T_ * D_;

#pragma unroll
    for (int it = 0; it < 4; it++) {
        int idx = it * 256 + tid;
        int r   = idx >> 4;
        int c4  = (idx & 15) * 4;
        float4 v = *(const float4*)(Qg + (size_t)(q0 + r) * D_ + c4);
        Qs[(c4 + 0) * ATS + r] = v.x * SCALE_;
        Qs[(c4 + 1) * ATS + r] = v.y * SCALE_;
        Qs[(c4 + 2) * ATS + r] = v.z * SCALE_;
        Qs[(c4 + 3) * ATS + r] = v.w * SCALE_;
    }

    float m[4], l[4], acc[4][4];
#pragma unroll
    for (int i = 0; i < 4; i++) {
        m[i] = -1e30f; l[i] = 0.f;
#pragma unroll
        for (int j = 0; j < 4; j++) acc[i][j] = 0.f;
    }

    for (int kt = 0; kt < T_ / 64; kt++) {
        __syncthreads();
#pragma unroll
        for (int it = 0; it < 4; it++) {
            int idx = it * 256 + tid;
            int r   = idx >> 4;
            int c4  = (idx & 15) * 4;
            float4 kv = *(const float4*)(Kg + (size_t)(kt * 64 + r) * D_ + c4);
            Ks[(c4 + 0) * ATS + r] = kv.x;
            Ks[(c4 + 1) * ATS + r] = kv.y;
            Ks[(c4 + 2) * ATS + r] = kv.z;
            Ks[(c4 + 3) * ATS + r] = kv.w;
            float4 vv = *(const float4*)(Vg + (size_t)(kt * 64 + r) * D_ + c4);
            *(float4*)&Vs[r * ATS + c4] = vv;
        }
        __syncthreads();

        float s[4][4];
#pragma unroll
        for (int i = 0; i < 4; i++)
#pragma unroll
            for (int j = 0; j < 4; j++) s[i][j] = 0.f;

#pragma unroll 8
        for (int d = 0; d < 64; d++) {
            float4 qa = *(const float4*)&Qs[d * ATS + ty * 4];
            float4 kb = *(const float4*)&Ks[d * ATS + tx * 4];
            float ra[4] = {qa.x, qa.y, qa.z, qa.w};
            float rb[4] = {kb.x, kb.y, kb.z, kb.w};
#pragma unroll
            for (int i = 0; i < 4; i++)
#pragma unroll
                for (int j = 0; j < 4; j++)
                    s[i][j] += ra[i] * rb[j];
        }
        __syncthreads();

#pragma unroll
        for (int i = 0; i < 4; i++) {
            float tm = fmaxf(fmaxf(s[i][0], s[i][1]), fmaxf(s[i][2], s[i][3]));
#pragma unroll
            for (int off = 8; off; off >>= 1)
                tm = fmaxf(tm, __shfl_xor_sync(0xffffffffu, tm, off));
            float mn = fmaxf(m[i], tm);
            float f  = __expf(m[i] - mn);
            m[i] = mn;
            float rs = 0.f;
#pragma unroll
            for (int j = 0; j < 4; j++) {
                float p = __expf(s[i][j] - mn);
                s[i][j] = p;
                rs += p;
            }
#pragma unroll
            for (int off = 8; off; off >>= 1)
                rs += __shfl_xor_sync(0xffffffffu, rs, off);
            l[i] = l[i] * f + rs;
#pragma unroll
            for (int j = 0; j < 4; j++) acc[i][j] *= f;
            *(float4*)&Ks[(ty * 4 + i) * ATS + tx * 4] =
                make_float4(s[i][0], s[i][1], s[i][2], s[i][3]);
        }
        __syncthreads();

#pragma unroll 4
        for (int k4 = 0; k4 < 64; k4 += 4) {
            float Pv[4][4], Vv[4][4];
#pragma unroll
            for (int i = 0; i < 4; i++)
                *(float4*)Pv[i] = *(const float4*)&Ks[(ty * 4 + i) * ATS + k4];
#pragma unroll
            for (int kk = 0; kk < 4; kk++)
                *(float4*)Vv[kk] = *(const float4*)&Vs[(k4 + kk) * ATS + tx * 4];
#pragma unroll
            for (int kk = 0; kk < 4; kk++)
#pragma unroll
                for (int i = 0; i < 4; i++)
#pragma unroll
                    for (int j = 0; j < 4; j++)
                        acc[i][j] += Pv[i][kk] * Vv[kk][j];
        }
    }

    const int b = bh / H_;
    const int h = bh - b * H_;
#pragma unroll
    for (int i = 0; i < 4; i++) {
        float inv = 1.f / l[i];
        int t = q0 + ty * 4 + i;
        float4 o = make_float4(acc[i][0] * inv, acc[i][1] * inv,
                               acc[i][2] * inv, acc[i][3] * inv);
        *(float4*)&g_ctx[(size_t)(b * T_ + t) * C_ + h * D_ + tx * 4] = o;
    }
}

// ---------------------------------------------------------------------------
extern "C" void kernel_launch(void* const* d_in, const int* in_sizes, int n_in,
                              void* d_out, int out_size)
{
    const float* hidden = (const float*)d_in[0];
    const float* qkv_w  = (const float*)d_in[1];
    const float* qkv_b  = (const float*)d_in[2];
    const float* proj_w = (const float*)d_in[3];
    const float* proj_b = (const float*)d_in[4];
    float* out = (float*)d_out;
    (void)in_sizes; (void)n_in; (void)out_size;

    cudaFuncSetAttribute(gemm_mma_kernel<0>,
                         cudaFuncAttributeMaxDynamicSharedMemorySize, GEMM_SMEM);
    cudaFuncSetAttribute(gemm_mma_kernel<1>,
                         cudaFuncAttributeMaxDynamicSharedMemorySize, GEMM_SMEM);
    const int attn_smem = 3 * 64 * ATS * (int)sizeof(float);
    cudaFuncSetAttribute(attn_kernel,
                         cudaFuncAttributeMaxDynamicSharedMemorySize, attn_smem);

    // 0) operand conversions
    conv_split_kernel<<<(M_ * C_) / 256, 256>>>(hidden, 0, M_ * C_);
    conv_transpose_kernel<<<dim3(N1_ / 32, C_ / 32), dim3(32, 8)>>>(qkv_w, 0, C_, N1_);
    conv_transpose_kernel<<<dim3(C_ / 32, C_ / 32), dim3(32, 8)>>>(proj_w, 1, C_, C_);

    // 1) QKV projection (mma.sync bf16x3) -> g_q / g_k / g_v
    gemm_mma_kernel<0><<<dim3(N1_ / 128, M_ / 128), 256, GEMM_SMEM>>>(qkv_b, nullptr);

    // 2) attention -> g_ctx
    attn_kernel<<<dim3(T_ / 64, B_ * H_), 256, attn_smem>>>();

    // 3) ctx conversion (device-internal source) + output projection
    conv_split_kernel<<<(M_ * C_) / 256, 256>>>(nullptr, 1, M_ * C_);
    gemm_mma_kernel<1><<<dim3(C_ / 128, M_ / 128), 256, GEMM_SMEM>>>(proj_b, out);
}

// round 7
// speedup vs baseline: 2.2805x; 1.6111x over previous
#include <cuda_runtime.h>
#include <cuda_bf16.h>
#include <cstdint>
#include <cstddef>

#define B_   8
#define T_   1024
#define C_   768
#define H_   12
#define D_   64
#define M_   (B_ * T_)     /* 8192 */
#define N1_  (3 * C_)      /* 2304 */

// ---------------- device-global scratch -------------------------------------
__device__ __nv_bfloat16 g_ahi[(size_t)M_ * C_];
__device__ __nv_bfloat16 g_alo[(size_t)M_ * C_];
__device__ __nv_bfloat16 g_chi[(size_t)M_ * C_];
__device__ __nv_bfloat16 g_clo[(size_t)M_ * C_];
__device__ __nv_bfloat16 g_wq_hi[(size_t)N1_ * C_];
__device__ __nv_bfloat16 g_wq_lo[(size_t)N1_ * C_];
__device__ __nv_bfloat16 g_wp_hi[(size_t)C_ * C_];
__device__ __nv_bfloat16 g_wp_lo[(size_t)C_ * C_];
// Q/K/V per-head [B*H, T, D] bf16 hi/lo (Q pre-scaled by 0.125)
__device__ __nv_bfloat16 g_qhi[(size_t)M_ * C_];
__device__ __nv_bfloat16 g_qlo[(size_t)M_ * C_];
__device__ __nv_bfloat16 g_khi[(size_t)M_ * C_];
__device__ __nv_bfloat16 g_klo[(size_t)M_ * C_];
__device__ __nv_bfloat16 g_vhi[(size_t)M_ * C_];
__device__ __nv_bfloat16 g_vlo[(size_t)M_ * C_];

// ---------------- PTX helpers ----------------------------------------------
__device__ __forceinline__ uint32_t smem_u32(const void* p) {
    uint32_t a;
    asm("{ .reg .u64 t; cvta.to.shared.u64 t, %1; cvt.u32.u64 %0, t; }"
        : "=r"(a) : "l"(p));
    return a;
}

#define CP_ASYNC16(dst, src) \
    asm volatile("cp.async.cg.shared.global [%0], [%1], 16;" \
                 :: "r"(dst), "l"(src) : "memory")
#define CP_COMMIT() asm volatile("cp.async.commit_group;" ::: "memory")
#define CP_WAIT(n)  asm volatile("cp.async.wait_group %0;" :: "n"(n) : "memory")

__device__ __forceinline__ void ldsm4(uint32_t* r, uint32_t a) {
    asm volatile("ldmatrix.sync.aligned.m8n8.x4.shared.b16 {%0,%1,%2,%3}, [%4];"
                 : "=r"(r[0]), "=r"(r[1]), "=r"(r[2]), "=r"(r[3]) : "r"(a));
}
__device__ __forceinline__ void ldsm4t(uint32_t* r, uint32_t a) {
    asm volatile("ldmatrix.sync.aligned.m8n8.x4.trans.shared.b16 {%0,%1,%2,%3}, [%4];"
                 : "=r"(r[0]), "=r"(r[1]), "=r"(r[2]), "=r"(r[3]) : "r"(a));
}

__device__ __forceinline__ void mma_bf16(float* c, const uint32_t* a,
                                         uint32_t b0, uint32_t b1) {
    asm volatile(
        "mma.sync.aligned.m16n8k16.row.col.f32.bf16.bf16.f32 "
        "{%0,%1,%2,%3}, {%4,%5,%6,%7}, {%8,%9}, {%0,%1,%2,%3};"
        : "+f"(c[0]), "+f"(c[1]), "+f"(c[2]), "+f"(c[3])
        : "r"(a[0]), "r"(a[1]), "r"(a[2]), "r"(a[3]), "r"(b0), "r"(b1));
}

__device__ __forceinline__ void split2(float x, float y, uint32_t& hi, uint32_t& lo) {
    __nv_bfloat16 hx = __float2bfloat16(x), hy = __float2bfloat16(y);
    __nv_bfloat16 lx = __float2bfloat16(x - __bfloat162float(hx));
    __nv_bfloat16 ly = __float2bfloat16(y - __bfloat162float(hy));
    hi = ((uint32_t)__bfloat16_as_ushort(hy) << 16) | (uint32_t)__bfloat16_as_ushort(hx);
    lo = ((uint32_t)__bfloat16_as_ushort(ly) << 16) | (uint32_t)__bfloat16_as_ushort(lx);
}

// ---------------- conversion kernels ----------------------------------------
__global__ void conv_split_kernel(const float* __restrict__ src, int n)
{
    int i = blockIdx.x * blockDim.x + threadIdx.x;
    if (i >= n) return;
    float x = src[i];
    __nv_bfloat16 h = __float2bfloat16(x);
    g_ahi[i] = h;
    g_alo[i] = __float2bfloat16(x - __bfloat162float(h));
}

__global__ void conv_transpose_kernel(const float* __restrict__ src, int dst_sel,
                                      int K, int N)
{
    __shared__ float tile[32][33];
    int kx = blockIdx.y * 32;
    int nx = blockIdx.x * 32;
    int tx = threadIdx.x;
    int ty = threadIdx.y;
    for (int i = ty; i < 32; i += 8)
        tile[i][tx] = src[(size_t)(kx + i) * N + nx + tx];
    __syncthreads();
    __nv_bfloat16* dhi = dst_sel ? g_wp_hi : g_wq_hi;
    __nv_bfloat16* dlo = dst_sel ? g_wp_lo : g_wq_lo;
    for (int i = ty; i < 32; i += 8) {
        float v = tile[tx][i];
        __nv_bfloat16 h = __float2bfloat16(v);
        size_t o = (size_t)(nx + i) * K + kx + tx;
        dhi[o] = h;
        dlo[o] = __float2bfloat16(v - __bfloat162float(h));
    }
}

// ---------------- mma.sync bf16x3 GEMM --------------------------------------
#define BKE 32
#define KSB 80
#define TILE_B (128 * KSB)
#define STAGE_B (4 * TILE_B)
#define GEMM_SMEM (2 * STAGE_B)
#define NKT 24

template <int MODE>
__global__ __launch_bounds__(256, 1)
void gemm_mma_kernel(const float* __restrict__ bias, float* __restrict__ out)
{
    extern __shared__ char smem[];
    const uint32_t sbase = smem_u32(smem);
    const int tid = threadIdx.x;
    const int wid = tid >> 5;
    const int l   = tid & 31;
    const int gm0 = blockIdx.y * 128;
    const int gn0 = blockIdx.x * 128;

    const __nv_bfloat16* gAhi = MODE ? g_chi : g_ahi;
    const __nv_bfloat16* gAlo = MODE ? g_clo : g_alo;
    const __nv_bfloat16* gBhi = MODE ? g_wp_hi : g_wq_hi;
    const __nv_bfloat16* gBlo = MODE ? g_wp_lo : g_wq_lo;

    const int m0 = (wid & 3) * 32;
    const int n0 = (wid >> 2) * 64;

    const int lq = l >> 3, lr = l & 7;
    const uint32_t a_off = (uint32_t)((m0 + (lq & 1) * 8 + lr) * KSB + ((lq >> 1) * 8) * 2);
    const uint32_t b_off = (uint32_t)((n0 + (lq >> 1) * 8 + lr) * KSB + ((lq & 1) * 8) * 2);

    float acc[2][8][4];
#pragma unroll
    for (int mt = 0; mt < 2; mt++)
#pragma unroll
        for (int nt = 0; nt < 8; nt++)
#pragma unroll
            for (int j = 0; j < 4; j++) acc[mt][nt][j] = 0.f;

    auto issue_stage = [&](int kt, int s) {
        const int k0 = kt * BKE;
        const uint32_t sb = sbase + (uint32_t)s * STAGE_B;
#pragma unroll
        for (int tile = 0; tile < 4; tile++) {
            const __nv_bfloat16* src =
                (tile == 0) ? gAhi : (tile == 1) ? gAlo : (tile == 2) ? gBhi : gBlo;
            const int g0 = (tile < 2) ? gm0 : gn0;
#pragma unroll
            for (int hf = 0; hf < 2; hf++) {
                int c   = hf * 256 + tid;
                int row = c >> 2;
                int ch  = c & 3;
                const void* gp = src + (size_t)(g0 + row) * C_ + k0 + ch * 8;
                uint32_t dp = sb + (uint32_t)tile * TILE_B + row * KSB + ch * 16;
                CP_ASYNC16(dp, gp);
            }
        }
    };

    issue_stage(0, 0);
    CP_COMMIT();

    for (int kt = 0; kt < NKT; kt++) {
        const int s = kt & 1;
        if (kt + 1 < NKT) {
            issue_stage(kt + 1, s ^ 1);
            CP_COMMIT();
            CP_WAIT(1);
        } else {
            CP_WAIT(0);
        }
        __syncthreads();

        const uint32_t sb = sbase + (uint32_t)s * STAGE_B;
        const uint32_t aHi = sb + a_off;
        const uint32_t aLo = sb + TILE_B + a_off;
        const uint32_t bHi = sb + 2 * TILE_B + b_off;
        const uint32_t bLo = sb + 3 * TILE_B + b_off;

#pragma unroll
        for (int kk = 0; kk < 2; kk++) {
            const uint32_t ko = kk * 32;
            uint32_t ah[2][4], al[2][4], bh[4][4], bl[4][4];
#pragma unroll
            for (int mt = 0; mt < 2; mt++) {
                ldsm4(ah[mt], aHi + mt * (16 * KSB) + ko);
                ldsm4(al[mt], aLo + mt * (16 * KSB) + ko);
            }
#pragma unroll
            for (int p = 0; p < 4; p++) {
                ldsm4(bh[p], bHi + p * (16 * KSB) + ko);
                ldsm4(bl[p], bLo + p * (16 * KSB) + ko);
            }
#pragma unroll
            for (int mt = 0; mt < 2; mt++)
#pragma unroll
                for (int nt = 0; nt < 8; nt++) {
                    const int p = nt >> 1, o = (nt & 1) * 2;
                    mma_bf16(acc[mt][nt], ah[mt], bh[p][o], bh[p][o + 1]);
                    mma_bf16(acc[mt][nt], ah[mt], bl[p][o], bl[p][o + 1]);
                    mma_bf16(acc[mt][nt], al[mt], bh[p][o], bh[p][o + 1]);
                }
        }
        __syncthreads();
    }

    // ---------------- epilogue ----------------------------------------------
    const int gr_base = gm0 + m0 + (l >> 2);
    const int gc_loc  = 2 * (l & 3);

    if (MODE == 0) {
        // write Q (pre-scaled), K, V as bf16 hi/lo [B*H, T, D]
        const int which    = gn0 / C_;
        const int rem_base = gn0 - which * C_;
        __nv_bfloat16* dhi = (which == 0) ? g_qhi : (which == 1) ? g_khi : g_vhi;
        __nv_bfloat16* dlo = (which == 0) ? g_qlo : (which == 1) ? g_klo : g_vlo;
        const float sc = (which == 0) ? 0.125f : 1.0f;
#pragma unroll
        for (int mt = 0; mt < 2; mt++)
#pragma unroll
            for (int nt = 0; nt < 8; nt++) {
                const float* c = acc[mt][nt];
                const int gcn = n0 + nt * 8 + gc_loc;
                const int gc  = gn0 + gcn;
                float2 bb = *(const float2*)&bias[gc];
                const int rem = rem_base + gcn;
                const int h = rem >> 6, d = rem & 63;
#pragma unroll
                for (int hf = 0; hf < 2; hf++) {
                    const int gr = gr_base + mt * 16 + hf * 8;
                    const int b  = gr >> 10, tq = gr & 1023;
                    float x = (c[hf * 2 + 0] + bb.x) * sc;
                    float y = (c[hf * 2 + 1] + bb.y) * sc;
                    uint32_t hi, lo;
                    split2(x, y, hi, lo);
                    size_t idx = (((size_t)(b * H_ + h)) * T_ + tq) * D_ + d;
                    *(uint32_t*)&dhi[idx] = hi;
                    *(uint32_t*)&dlo[idx] = lo;
                }
            }
    } else {
#pragma unroll
        for (int mt = 0; mt < 2; mt++)
#pragma unroll
            for (int nt = 0; nt < 8; nt++) {
                const float* c = acc[mt][nt];
                const int gc = gn0 + n0 + nt * 8 + gc_loc;
                float2 bb = *(const float2*)&bias[gc];
#pragma unroll
                for (int hf = 0; hf < 2; hf++) {
                    const int gr = gr_base + mt * 16 + hf * 8;
                    float2 o;
                    o.x = c[hf * 2 + 0] + bb.x;
                    o.y = c[hf * 2 + 1] + bb.y;
                    *(float2*)&out[(size_t)gr * C_ + gc] = o;
                }
            }
    }
}

// ---------------- tensor-core flash attention (bf16x3) ----------------------
// CTA: 128 q-rows x one (b,h). 8 warps x 16 rows. BK=64 keys, 16 iters.
#define NT_  16
#define ROWB 144                     /* 72 bf16 row stride */
#define SQ_HI 0
#define SQ_LO 18432
#define SK(s) (36864 + (s) * 18432)  /* khi +0, klo +9216 */
#define SV(s) (73728 + (s) * 18432)  /* vhi +0, vlo +9216 */
#define SP_HI 110592
#define SP_LO 129024
#define ATTN_SMEM 147456

__global__ __launch_bounds__(256, 1) void attn_mma_kernel()
{
    extern __shared__ char smem[];
    const uint32_t sbase = smem_u32(smem);
    const int tid = threadIdx.x, wid = tid >> 5, l = tid & 31;
    const int bh = blockIdx.y, q0 = blockIdx.x * 128;
    const size_t hb = (size_t)bh * T_ * D_;
    const __nv_bfloat16 *Qh = g_qhi + hb, *Ql = g_qlo + hb;
    const __nv_bfloat16 *Kh = g_khi + hb, *Kl = g_klo + hb;
    const __nv_bfloat16 *Vh = g_vhi + hb, *Vl = g_vlo + hb;

    const int m0 = wid * 16;
    const int lq = l >> 3, lr = l & 7;
    const uint32_t a_off = (uint32_t)((m0 + (lq & 1) * 8 + lr) * ROWB + (lq >> 1) * 16);
    const uint32_t b_off = (uint32_t)(((lq >> 1) * 8 + lr) * ROWB + (lq & 1) * 16);
    const uint32_t v_off = (uint32_t)(((lq & 1) * 8 + lr) * ROWB + (lq >> 1) * 16);

    // ---- load Q tile (hi/lo), 128 rows x 8 chunks each ----
#pragma unroll
    for (int a = 0; a < 2; a++) {
        const __nv_bfloat16* src = a ? Ql : Qh;
        const uint32_t dst = sbase + (a ? SQ_LO : SQ_HI);
#pragma unroll
        for (int it = 0; it < 4; it++) {
            int c = it * 256 + tid;
            int row = c >> 3, ch = c & 7;
            CP_ASYNC16(dst + row * ROWB + ch * 16,
                       src + (size_t)(q0 + row) * D_ + ch * 8);
        }
    }
    auto load_kv = [&](int kt, int s) {
        const int r0 = kt * 64;
#pragma unroll
        for (int a = 0; a < 4; a++) {
            const __nv_bfloat16* src = (a == 0) ? Kh : (a == 1) ? Kl
                                     : (a == 2) ? Vh : Vl;
            const uint32_t dst = sbase + ((a < 2) ? SK(s) : SV(s)) + (a & 1) * 9216;
#pragma unroll
            for (int it = 0; it < 2; it++) {
                int c = it * 256 + tid;
                int row = c >> 3, ch = c & 7;
                CP_ASYNC16(dst + row * ROWB + ch * 16,
                           src + (size_t)(r0 + row) * D_ + ch * 8);
            }
        }
    };
    load_kv(0, 0);
    CP_COMMIT();
    CP_WAIT(0);
    __syncthreads();

    // ---- Q fragments: persist in registers across all key tiles ----
    uint32_t qh[4][4], ql[4][4];
#pragma unroll
    for (int kk = 0; kk < 4; kk++) {
        ldsm4(qh[kk], sbase + SQ_HI + a_off + kk * 32);
        ldsm4(ql[kk], sbase + SQ_LO + a_off + kk * 32);
    }

    float mrow[2] = {-1e30f, -1e30f}, lsum[2] = {0.f, 0.f};
    float acc[8][4];
#pragma unroll
    for (int nt = 0; nt < 8; nt++)
#pragma unroll
        for (int j = 0; j < 4; j++) acc[nt][j] = 0.f;

    const uint32_t prow0 = (uint32_t)((m0 + (l >> 2)) * ROWB + (l & 3) * 4);

    for (int kt = 0; kt < NT_; kt++) {
        const int s = kt & 1;
        __syncthreads();                       // all warps done with prev iter reads
        if (kt + 1 < NT_) {
            load_kv(kt + 1, s ^ 1);
            CP_COMMIT();
            CP_WAIT(1);
        } else {
            CP_WAIT(0);
        }
        __syncthreads();                       // K/V buffer s ready for everyone

        // ---- S = Q K^T (bf16x3) ----
        float sc[8][4];
#pragma unroll
        for (int nt = 0; nt < 8; nt++)
#pragma unroll
            for (int j = 0; j < 4; j++) sc[nt][j] = 0.f;

        const uint32_t kbh = sbase + SK(s) + b_off;
        const uint32_t kbl = kbh + 9216;
#pragma unroll
        for (int kk = 0; kk < 4; kk++) {
            uint32_t bh4[4][4], bl4[4][4];
#pragma unroll
            for (int p = 0; p < 4; p++) {
                ldsm4(bh4[p], kbh + p * (16 * ROWB) + kk * 32);
                ldsm4(bl4[p], kbl + p * (16 * ROWB) + kk * 32);
            }
#pragma unroll
            for (int nt = 0; nt < 8; nt++) {
                const int p = nt >> 1, o = (nt & 1) * 2;
                mma_bf16(sc[nt], qh[kk], bh4[p][o], bh4[p][o + 1]);
                mma_bf16(sc[nt], qh[kk], bl4[p][o], bl4[p][o + 1]);
                mma_bf16(sc[nt], ql[kk], bh4[p][o], bh4[p][o + 1]);
            }
        }

        // ---- online softmax (rows l>>2 and l>>2+8 of warp tile) ----
        float mx0 = sc[0][0], mx1 = sc[0][2];
#pragma unroll
        for (int nt = 0; nt < 8; nt++) {
            mx0 = fmaxf(mx0, fmaxf(sc[nt][0], sc[nt][1]));
            mx1 = fmaxf(mx1, fmaxf(sc[nt][2], sc[nt][3]));
        }
        mx0 = fmaxf(mx0, __shfl_xor_sync(0xffffffffu, mx0, 1));
        mx0 = fmaxf(mx0, __shfl_xor_sync(0xffffffffu, mx0, 2));
        mx1 = fmaxf(mx1, __shfl_xor_sync(0xffffffffu, mx1, 1));
        mx1 = fmaxf(mx1, __shfl_xor_sync(0xffffffffu, mx1, 2));
        const float mn0 = fmaxf(mrow[0], mx0);
        const float mn1 = fmaxf(mrow[1], mx1);
        const float f0 = __expf(mrow[0] - mn0);
        const float f1 = __expf(mrow[1] - mn1);
        mrow[0] = mn0; mrow[1] = mn1;

        float rs0 = 0.f, rs1 = 0.f;
#pragma unroll
        for (int nt = 0; nt < 8; nt++) {
            float p0 = __expf(sc[nt][0] - mn0);
            float p1 = __expf(sc[nt][1] - mn0);
            float p2 = __expf(sc[nt][2] - mn1);
            float p3 = __expf(sc[nt][3] - mn1);
            rs0 += p0 + p1; rs1 += p2 + p3;
            uint32_t h01, l01, h23, l23;
            split2(p0, p1, h01, l01);
            split2(p2, p3, h23, l23);
            const uint32_t o0 = prow0 + nt * 16;
            *(uint32_t*)(smem + SP_HI + o0) = h01;
            *(uint32_t*)(smem + SP_LO + o0) = l01;
            *(uint32_t*)(smem + SP_HI + o0 + 8 * ROWB) = h23;
            *(uint32_t*)(smem + SP_LO + o0 + 8 * ROWB) = l23;
            acc[nt][0] *= f0; acc[nt][1] *= f0;
            acc[nt][2] *= f1; acc[nt][3] *= f1;
        }
        rs0 += __shfl_xor_sync(0xffffffffu, rs0, 1);
        rs0 += __shfl_xor_sync(0xffffffffu, rs0, 2);
        rs1 += __shfl_xor_sync(0xffffffffu, rs1, 1);
        rs1 += __shfl_xor_sync(0xffffffffu, rs1, 2);
        lsum[0] = lsum[0] * f0 + rs0;
        lsum[1] = lsum[1] * f1 + rs1;
        __syncwarp();                          // P is warp-private (own 16 rows)

        // ---- O += P V (bf16x3) ----
        const uint32_t pbh = sbase + SP_HI + a_off;
        const uint32_t pbl = sbase + SP_LO + a_off;
        const uint32_t vbh = sbase + SV(s) + v_off;
        const uint32_t vbl = vbh + 9216;
#pragma unroll
        for (int kk = 0; kk < 4; kk++) {
            uint32_t ph[4], pl[4];
            ldsm4(ph, pbh + kk * 32);
            ldsm4(pl, pbl + kk * 32);
            uint32_t vh4[4][4], vl4[4][4];
#pragma unroll
            for (int p = 0; p < 4; p++) {
                ldsm4t(vh4[p], vbh + kk * (16 * ROWB) + p * 32);
                ldsm4t(vl4[p], vbl + kk * (16 * ROWB) + p * 32);
            }
#pragma unroll
            for (int nt = 0; nt < 8; nt++) {
                const int p = nt >> 1, o = (nt & 1) * 2;
                mma_bf16(acc[nt], ph, vh4[p][o], vh4[p][o + 1]);
                mma_bf16(acc[nt], ph, vl4[p][o], vl4[p][o + 1]);
                mma_bf16(acc[nt], pl, vh4[p][o], vh4[p][o + 1]);
            }
        }
    }

    // ---- epilogue: ctx -> bf16 hi/lo [B*T, C] -------------------------------
    const int b = bh / H_, h = bh - b * H_;
    const float i0 = 1.f / lsum[0];
    const float i1 = 1.f / lsum[1];
    const int r0 = q0 + m0 + (l >> 2);
    const size_t base0 = ((size_t)b * T_ + r0) * C_ + h * D_ + 2 * (l & 3);
    const size_t base1 = base0 + 8 * (size_t)C_;
#pragma unroll
    for (int nt = 0; nt < 8; nt++) {
        uint32_t hi, lo;
        split2(acc[nt][0] * i0, acc[nt][1] * i0, hi, lo);
        *(uint32_t*)&g_chi[base0 + nt * 8] = hi;
        *(uint32_t*)&g_clo[base0 + nt * 8] = lo;
        split2(acc[nt][2] * i1, acc[nt][3] * i1, hi, lo);
        *(uint32_t*)&g_chi[base1 + nt * 8] = hi;
        *(uint32_t*)&g_clo[base1 + nt * 8] = lo;
    }
}

// ---------------------------------------------------------------------------
extern "C" void kernel_launch(void* const* d_in, const int* in_sizes, int n_in,
                              void* d_out, int out_size)
{
    const float* hidden = (const float*)d_in[0];
    const float* qkv_w  = (const float*)d_in[1];
    const float* qkv_b  = (const float*)d_in[2];
    const float* proj_w = (const float*)d_in[3];
    const float* proj_b = (const float*)d_in[4];
    float* out = (float*)d_out;
    (void)in_sizes; (void)n_in; (void)out_size;

    cudaFuncSetAttribute(gemm_mma_kernel<0>,
                         cudaFuncAttributeMaxDynamicSharedMemorySize, GEMM_SMEM);
    cudaFuncSetAttribute(gemm_mma_kernel<1>,
                         cudaFuncAttributeMaxDynamicSharedMemorySize, GEMM_SMEM);
    cudaFuncSetAttribute(attn_mma_kernel,
                         cudaFuncAttributeMaxDynamicSharedMemorySize, ATTN_SMEM);

    // 0) operand conversions
    conv_split_kernel<<<(M_ * C_) / 256, 256>>>(hidden, M_ * C_);
    conv_transpose_kernel<<<dim3(N1_ / 32, C_ / 32), dim3(32, 8)>>>(qkv_w, 0, C_, N1_);
    conv_transpose_kernel<<<dim3(C_ / 32, C_ / 32), dim3(32, 8)>>>(proj_w, 1, C_, C_);

    // 1) QKV projection -> Q/K/V bf16 hi/lo (Q pre-scaled)
    gemm_mma_kernel<0><<<dim3(N1_ / 128, M_ / 128), 256, GEMM_SMEM>>>(qkv_b, nullptr);

    // 2) attention -> ctx bf16 hi/lo
    attn_mma_kernel<<<dim3(T_ / 128, B_ * H_), 256, ATTN_SMEM>>>();

    // 3) output projection
    gemm_mma_kernel<1><<<dim3(C_ / 128, M_ / 128), 256, GEMM_SMEM>>>(proj_b, out);
}

// round 8
// speedup vs baseline: 2.3675x; 1.0381x over previous
#include <cuda_runtime.h>
#include <cuda_bf16.h>
#include <cstdint>
#include <cstddef>

#define B_   8
#define T_   1024
#define C_   768
#define H_   12
#define D_   64
#define M_   (B_ * T_)     /* 8192 */
#define N1_  (3 * C_)      /* 2304 */

// ---------------- device-global scratch -------------------------------------
__device__ __nv_bfloat16 g_ahi[(size_t)M_ * C_];
__device__ __nv_bfloat16 g_alo[(size_t)M_ * C_];
__device__ __nv_bfloat16 g_chi[(size_t)M_ * C_];
__device__ __nv_bfloat16 g_clo[(size_t)M_ * C_];
__device__ __nv_bfloat16 g_wq_hi[(size_t)N1_ * C_];
__device__ __nv_bfloat16 g_wq_lo[(size_t)N1_ * C_];
__device__ __nv_bfloat16 g_wp_hi[(size_t)C_ * C_];
__device__ __nv_bfloat16 g_wp_lo[(size_t)C_ * C_];
// Q/K/V per-head [B*H, T, D] bf16 hi/lo (Q pre-scaled by 0.125)
__device__ __nv_bfloat16 g_qhi[(size_t)M_ * C_];
__device__ __nv_bfloat16 g_qlo[(size_t)M_ * C_];
__device__ __nv_bfloat16 g_khi[(size_t)M_ * C_];
__device__ __nv_bfloat16 g_klo[(size_t)M_ * C_];
__device__ __nv_bfloat16 g_vhi[(size_t)M_ * C_];
__device__ __nv_bfloat16 g_vlo[(size_t)M_ * C_];

// ---------------- PTX helpers ----------------------------------------------
__device__ __forceinline__ uint32_t smem_u32(const void* p) {
    uint32_t a;
    asm("{ .reg .u64 t; cvta.to.shared.u64 t, %1; cvt.u32.u64 %0, t; }"
        : "=r"(a) : "l"(p));
    return a;
}

#define CP_ASYNC16(dst, src) \
    asm volatile("cp.async.cg.shared.global [%0], [%1], 16;" \
                 :: "r"(dst), "l"(src) : "memory")
#define CP_COMMIT() asm volatile("cp.async.commit_group;" ::: "memory")
#define CP_WAIT(n)  asm volatile("cp.async.wait_group %0;" :: "n"(n) : "memory")

__device__ __forceinline__ void ldsm4(uint32_t* r, uint32_t a) {
    asm volatile("ldmatrix.sync.aligned.m8n8.x4.shared.b16 {%0,%1,%2,%3}, [%4];"
                 : "=r"(r[0]), "=r"(r[1]), "=r"(r[2]), "=r"(r[3]) : "r"(a));
}
__device__ __forceinline__ void ldsm4t(uint32_t* r, uint32_t a) {
    asm volatile("ldmatrix.sync.aligned.m8n8.x4.trans.shared.b16 {%0,%1,%2,%3}, [%4];"
                 : "=r"(r[0]), "=r"(r[1]), "=r"(r[2]), "=r"(r[3]) : "r"(a));
}

__device__ __forceinline__ void mma_bf16(float* c, const uint32_t* a,
                                         uint32_t b0, uint32_t b1) {
    asm volatile(
        "mma.sync.aligned.m16n8k16.row.col.f32.bf16.bf16.f32 "
        "{%0,%1,%2,%3}, {%4,%5,%6,%7}, {%8,%9}, {%0,%1,%2,%3};"
        : "+f"(c[0]), "+f"(c[1]), "+f"(c[2]), "+f"(c[3])
        : "r"(a[0]), "r"(a[1]), "r"(a[2]), "r"(a[3]), "r"(b0), "r"(b1));
}

__device__ __forceinline__ void split2(float x, float y, uint32_t& hi, uint32_t& lo) {
    __nv_bfloat16 hx = __float2bfloat16(x), hy = __float2bfloat16(y);
    __nv_bfloat16 lx = __float2bfloat16(x - __bfloat162float(hx));
    __nv_bfloat16 ly = __float2bfloat16(y - __bfloat162float(hy));
    hi = ((uint32_t)__bfloat16_as_ushort(hy) << 16) | (uint32_t)__bfloat16_as_ushort(hx);
    lo = ((uint32_t)__bfloat16_as_ushort(ly) << 16) | (uint32_t)__bfloat16_as_ushort(lx);
}

// ---------------- conversion kernels ----------------------------------------
__global__ void conv_split_kernel(const float* __restrict__ src, int n)
{
    int i = blockIdx.x * blockDim.x + threadIdx.x;
    if (i >= n) return;
    float x = src[i];
    __nv_bfloat16 h = __float2bfloat16(x);
    g_ahi[i] = h;
    g_alo[i] = __float2bfloat16(x - __bfloat162float(h));
}

__global__ void conv_transpose_kernel(const float* __restrict__ src, int dst_sel,
                                      int K, int N)
{
    __shared__ float tile[32][33];
    int kx = blockIdx.y * 32;
    int nx = blockIdx.x * 32;
    int tx = threadIdx.x;
    int ty = threadIdx.y;
    for (int i = ty; i < 32; i += 8)
        tile[i][tx] = src[(size_t)(kx + i) * N + nx + tx];
    __syncthreads();
    __nv_bfloat16* dhi = dst_sel ? g_wp_hi : g_wq_hi;
    __nv_bfloat16* dlo = dst_sel ? g_wp_lo : g_wq_lo;
    for (int i = ty; i < 32; i += 8) {
        float v = tile[tx][i];
        __nv_bfloat16 h = __float2bfloat16(v);
        size_t o = (size_t)(nx + i) * K + kx + tx;
        dhi[o] = h;
        dlo[o] = __float2bfloat16(v - __bfloat162float(h));
    }
}

// ---------------- mma.sync bf16x3 GEMM (512 thr, 4x4 warps, 3-stage) --------
#define BKE 32
#define KSB 80
#define TILE_B (128 * KSB)           /* 10240 */
#define STAGE_B (4 * TILE_B)         /* 40960 */
#define NSTG 3
#define GEMM_SMEM (NSTG * STAGE_B)   /* 122880 */
#define NKT 24

template <int MODE>
__global__ __launch_bounds__(512, 1)
void gemm_mma_kernel(const float* __restrict__ bias, float* __restrict__ out)
{
    extern __shared__ char smem[];
    const uint32_t sbase = smem_u32(smem);
    const int tid = threadIdx.x;
    const int wid = tid >> 5;          // 0..15
    const int l   = tid & 31;
    const int gm0 = blockIdx.y * 128;
    const int gn0 = blockIdx.x * 128;

    const __nv_bfloat16* gAhi = MODE ? g_chi : g_ahi;
    const __nv_bfloat16* gAlo = MODE ? g_clo : g_alo;
    const __nv_bfloat16* gBhi = MODE ? g_wp_hi : g_wq_hi;
    const __nv_bfloat16* gBlo = MODE ? g_wp_lo : g_wq_lo;

    const int m0 = (wid & 3) * 32;     // warp rows
    const int n0 = (wid >> 2) * 32;    // warp cols

    const int lq = l >> 3, lr = l & 7;
    const uint32_t a_off = (uint32_t)((m0 + (lq & 1) * 8 + lr) * KSB + ((lq >> 1) * 8) * 2);
    const uint32_t b_off = (uint32_t)((n0 + (lq >> 1) * 8 + lr) * KSB + ((lq & 1) * 8) * 2);

    float acc[2][4][4];
#pragma unroll
    for (int mt = 0; mt < 2; mt++)
#pragma unroll
        for (int nt = 0; nt < 4; nt++)
#pragma unroll
            for (int j = 0; j < 4; j++) acc[mt][nt][j] = 0.f;

    // loader: 4 tiles x 512 16B-chunks; 512 threads -> 1 chunk/thread/tile
    const int lrow = tid >> 2;            // 0..127
    const int lch  = tid & 3;             // 0..3
    auto issue_stage = [&](int kt, int s) {
        const int k0 = kt * BKE;
        const uint32_t sb = sbase + (uint32_t)s * STAGE_B;
#pragma unroll
        for (int tile = 0; tile < 4; tile++) {
            const __nv_bfloat16* src =
                (tile == 0) ? gAhi : (tile == 1) ? gAlo : (tile == 2) ? gBhi : gBlo;
            const int g0 = (tile < 2) ? gm0 : gn0;
            const void* gp = src + (size_t)(g0 + lrow) * C_ + k0 + lch * 8;
            uint32_t dp = sb + (uint32_t)tile * TILE_B + lrow * KSB + lch * 16;
            CP_ASYNC16(dp, gp);
        }
    };

    issue_stage(0, 0); CP_COMMIT();
    issue_stage(1, 1); CP_COMMIT();

#pragma unroll 1
    for (int kt = 0; kt < NKT; kt++) {
        const int s = kt % NSTG;
        if (kt + 1 < NKT) { CP_WAIT(1); } else { CP_WAIT(0); }
        __syncthreads();
        if (kt + 2 < NKT) {
            issue_stage(kt + 2, (kt + 2) % NSTG);
            CP_COMMIT();
        }

        const uint32_t sb = sbase + (uint32_t)s * STAGE_B;
        const uint32_t aHi = sb + a_off;
        const uint32_t aLo = sb + TILE_B + a_off;
        const uint32_t bHi = sb + 2 * TILE_B + b_off;
        const uint32_t bLo = sb + 3 * TILE_B + b_off;

#pragma unroll
        for (int kk = 0; kk < 2; kk++) {
            const uint32_t ko = kk * 32;
            uint32_t ah[2][4], al[2][4], bh[2][4], bl[2][4];
#pragma unroll
            for (int mt = 0; mt < 2; mt++) {
                ldsm4(ah[mt], aHi + mt * (16 * KSB) + ko);
                ldsm4(al[mt], aLo + mt * (16 * KSB) + ko);
            }
#pragma unroll
            for (int p = 0; p < 2; p++) {
                ldsm4(bh[p], bHi + p * (16 * KSB) + ko);
                ldsm4(bl[p], bLo + p * (16 * KSB) + ko);
            }
#pragma unroll
            for (int mt = 0; mt < 2; mt++)
#pragma unroll
                for (int nt = 0; nt < 4; nt++) {
                    const int p = nt >> 1, o = (nt & 1) * 2;
                    mma_bf16(acc[mt][nt], ah[mt], bh[p][o], bh[p][o + 1]);
                    mma_bf16(acc[mt][nt], ah[mt], bl[p][o], bl[p][o + 1]);
                    mma_bf16(acc[mt][nt], al[mt], bh[p][o], bh[p][o + 1]);
                }
        }
    }

    // ---------------- epilogue ----------------------------------------------
    const int gr_base = gm0 + m0 + (l >> 2);
    const int gc_loc  = 2 * (l & 3);

    if (MODE == 0) {
        const int which    = gn0 / C_;
        const int rem_base = gn0 - which * C_;
        __nv_bfloat16* dhi = (which == 0) ? g_qhi : (which == 1) ? g_khi : g_vhi;
        __nv_bfloat16* dlo = (which == 0) ? g_qlo : (which == 1) ? g_klo : g_vlo;
        const float sc = (which == 0) ? 0.125f : 1.0f;
#pragma unroll
        for (int mt = 0; mt < 2; mt++)
#pragma unroll
            for (int nt = 0; nt < 4; nt++) {
                const float* c = acc[mt][nt];
                const int gcn = n0 + nt * 8 + gc_loc;
                const int gc  = gn0 + gcn;
                float2 bb = *(const float2*)&bias[gc];
                const int rem = rem_base + gcn;
                const int h = rem >> 6, d = rem & 63;
#pragma unroll
                for (int hf = 0; hf < 2; hf++) {
                    const int gr = gr_base + mt * 16 + hf * 8;
                    const int b  = gr >> 10, tq = gr & 1023;
                    float x = (c[hf * 2 + 0] + bb.x) * sc;
                    float y = (c[hf * 2 + 1] + bb.y) * sc;
                    uint32_t hi, lo;
                    split2(x, y, hi, lo);
                    size_t idx = (((size_t)(b * H_ + h)) * T_ + tq) * D_ + d;
                    *(uint32_t*)&dhi[idx] = hi;
                    *(uint32_t*)&dlo[idx] = lo;
                }
            }
    } else {
#pragma unroll
        for (int mt = 0; mt < 2; mt++)
#pragma unroll
            for (int nt = 0; nt < 4; nt++) {
                const float* c = acc[mt][nt];
                const int gc = gn0 + n0 + nt * 8 + gc_loc;
                float2 bb = *(const float2*)&bias[gc];
#pragma unroll
                for (int hf = 0; hf < 2; hf++) {
                    const int gr = gr_base + mt * 16 + hf * 8;
                    float2 o;
                    o.x = c[hf * 2 + 0] + bb.x;
                    o.y = c[hf * 2 + 1] + bb.y;
                    *(float2*)&out[(size_t)gr * C_ + gc] = o;
                }
            }
    }
}

// ---------------- tensor-core flash attention (bf16x3, unchanged R7) --------
#define NT_  16
#define ROWB 144
#define SQ_HI 0
#define SQ_LO 18432
#define SK(s) (36864 + (s) * 18432)
#define SV(s) (73728 + (s) * 18432)
#define SP_HI 110592
#define SP_LO 129024
#define ATTN_SMEM 147456

__global__ __launch_bounds__(256, 1) void attn_mma_kernel()
{
    extern __shared__ char smem[];
    const uint32_t sbase = smem_u32(smem);
    const int tid = threadIdx.x, wid = tid >> 5, l = tid & 31;
    const int bh = blockIdx.y, q0 = blockIdx.x * 128;
    const size_t hb = (size_t)bh * T_ * D_;
    const __nv_bfloat16 *Qh = g_qhi + hb, *Ql = g_qlo + hb;
    const __nv_bfloat16 *Kh = g_khi + hb, *Kl = g_klo + hb;
    const __nv_bfloat16 *Vh = g_vhi + hb, *Vl = g_vlo + hb;

    const int m0 = wid * 16;
    const int lq = l >> 3, lr = l & 7;
    const uint32_t a_off = (uint32_t)((m0 + (lq & 1) * 8 + lr) * ROWB + (lq >> 1) * 16);
    const uint32_t b_off = (uint32_t)(((lq >> 1) * 8 + lr) * ROWB + (lq & 1) * 16);
    const uint32_t v_off = (uint32_t)(((lq & 1) * 8 + lr) * ROWB + (lq >> 1) * 16);

#pragma unroll
    for (int a = 0; a < 2; a++) {
        const __nv_bfloat16* src = a ? Ql : Qh;
        const uint32_t dst = sbase + (a ? SQ_LO : SQ_HI);
#pragma unroll
        for (int it = 0; it < 4; it++) {
            int c = it * 256 + tid;
            int row = c >> 3, ch = c & 7;
            CP_ASYNC16(dst + row * ROWB + ch * 16,
                       src + (size_t)(q0 + row) * D_ + ch * 8);
        }
    }
    auto load_kv = [&](int kt, int s) {
        const int r0 = kt * 64;
#pragma unroll
        for (int a = 0; a < 4; a++) {
            const __nv_bfloat16* src = (a == 0) ? Kh : (a == 1) ? Kl
                                     : (a == 2) ? Vh : Vl;
            const uint32_t dst = sbase + ((a < 2) ? SK(s) : SV(s)) + (a & 1) * 9216;
#pragma unroll
            for (int it = 0; it < 2; it++) {
                int c = it * 256 + tid;
                int row = c >> 3, ch = c & 7;
                CP_ASYNC16(dst + row * ROWB + ch * 16,
                           src + (size_t)(r0 + row) * D_ + ch * 8);
            }
        }
    };
    load_kv(0, 0);
    CP_COMMIT();
    CP_WAIT(0);
    __syncthreads();

    uint32_t qh[4][4], ql[4][4];
#pragma unroll
    for (int kk = 0; kk < 4; kk++) {
        ldsm4(qh[kk], sbase + SQ_HI + a_off + kk * 32);
        ldsm4(ql[kk], sbase + SQ_LO + a_off + kk * 32);
    }

    float mrow[2] = {-1e30f, -1e30f}, lsum[2] = {0.f, 0.f};
    float acc[8][4];
#pragma unroll
    for (int nt = 0; nt < 8; nt++)
#pragma unroll
        for (int j = 0; j < 4; j++) acc[nt][j] = 0.f;

    const uint32_t prow0 = (uint32_t)((m0 + (l >> 2)) * ROWB + (l & 3) * 4);

    for (int kt = 0; kt < NT_; kt++) {
        const int s = kt & 1;
        __syncthreads();
        if (kt + 1 < NT_) {
            load_kv(kt + 1, s ^ 1);
            CP_COMMIT();
            CP_WAIT(1);
        } else {
            CP_WAIT(0);
        }
        __syncthreads();

        float sc[8][4];
#pragma unroll
        for (int nt = 0; nt < 8; nt++)
#pragma unroll
            for (int j = 0; j < 4; j++) sc[nt][j] = 0.f;

        const uint32_t kbh = sbase + SK(s) + b_off;
        const uint32_t kbl = kbh + 9216;
#pragma unroll
        for (int kk = 0; kk < 4; kk++) {
            uint32_t bh4[4][4], bl4[4][4];
#pragma unroll
            for (int p = 0; p < 4; p++) {
                ldsm4(bh4[p], kbh + p * (16 * ROWB) + kk * 32);
                ldsm4(bl4[p], kbl + p * (16 * ROWB) + kk * 32);
            }
#pragma unroll
            for (int nt = 0; nt < 8; nt++) {
                const int p = nt >> 1, o = (nt & 1) * 2;
                mma_bf16(sc[nt], qh[kk], bh4[p][o], bh4[p][o + 1]);
                mma_bf16(sc[nt], qh[kk], bl4[p][o], bl4[p][o + 1]);
                mma_bf16(sc[nt], ql[kk], bh4[p][o], bh4[p][o + 1]);
            }
        }

        float mx0 = sc[0][0], mx1 = sc[0][2];
#pragma unroll
        for (int nt = 0; nt < 8; nt++) {
            mx0 = fmaxf(mx0, fmaxf(sc[nt][0], sc[nt][1]));
            mx1 = fmaxf(mx1, fmaxf(sc[nt][2], sc[nt][3]));
        }
        mx0 = fmaxf(mx0, __shfl_xor_sync(0xffffffffu, mx0, 1));
        mx0 = fmaxf(mx0, __shfl_xor_sync(0xffffffffu, mx0, 2));
        mx1 = fmaxf(mx1, __shfl_xor_sync(0xffffffffu, mx1, 1));
        mx1 = fmaxf(mx1, __shfl_xor_sync(0xffffffffu, mx1, 2));
        const float mn0 = fmaxf(mrow[0], mx0);
        const float mn1 = fmaxf(mrow[1], mx1);
        const float f0 = __expf(mrow[0] - mn0);
        const float f1 = __expf(mrow[1] - mn1);
        mrow[0] = mn0; mrow[1] = mn1;

        float rs0 = 0.f, rs1 = 0.f;
#pragma unroll
        for (int nt = 0; nt < 8; nt++) {
            float p0 = __expf(sc[nt][0] - mn0);
            float p1 = __expf(sc[nt][1] - mn0);
            float p2 = __expf(sc[nt][2] - mn1);
            float p3 = __expf(sc[nt][3] - mn1);
            rs0 += p0 + p1; rs1 += p2 + p3;
            uint32_t h01, l01, h23, l23;
            split2(p0, p1, h01, l01);
            split2(p2, p3, h23, l23);
            const uint32_t o0 = prow0 + nt * 16;
            *(uint32_t*)(smem + SP_HI + o0) = h01;
            *(uint32_t*)(smem + SP_LO + o0) = l01;
            *(uint32_t*)(smem + SP_HI + o0 + 8 * ROWB) = h23;
            *(uint32_t*)(smem + SP_LO + o0 + 8 * ROWB) = l23;
            acc[nt][0] *= f0; acc[nt][1] *= f0;
            acc[nt][2] *= f1; acc[nt][3] *= f1;
        }
        rs0 += __shfl_xor_sync(0xffffffffu, rs0, 1);
        rs0 += __shfl_xor_sync(0xffffffffu, rs0, 2);
        rs1 += __shfl_xor_sync(0xffffffffu, rs1, 1);
        rs1 += __shfl_xor_sync(0xffffffffu, rs1, 2);
        lsum[0] = lsum[0] * f0 + rs0;
        lsum[1] = lsum[1] * f1 + rs1;
        __syncwarp();

        const uint32_t pbh = sbase + SP_HI + a_off;
        const uint32_t pbl = sbase + SP_LO + a_off;
        const uint32_t vbh = sbase + SV(s) + v_off;
        const uint32_t vbl = vbh + 9216;
#pragma unroll
        for (int kk = 0; kk < 4; kk++) {
            uint32_t ph[4], pl[4];
            ldsm4(ph, pbh + kk * 32);
            ldsm4(pl, pbl + kk * 32);
            uint32_t vh4[4][4], vl4[4][4];
#pragma unroll
            for (int p = 0; p < 4; p++) {
                ldsm4t(vh4[p], vbh + kk * (16 * ROWB) + p * 32);
                ldsm4t(vl4[p], vbl + kk * (16 * ROWB) + p * 32);
            }
#pragma unroll
            for (int nt = 0; nt < 8; nt++) {
                const int p = nt >> 1, o = (nt & 1) * 2;
                mma_bf16(acc[nt], ph, vh4[p][o], vh4[p][o + 1]);
                mma_bf16(acc[nt], ph, vl4[p][o], vl4[p][o + 1]);
                mma_bf16(acc[nt], pl, vh4[p][o], vh4[p][o + 1]);
            }
        }
    }

    const int b = bh / H_, h = bh - b * H_;
    const float i0 = 1.f / lsum[0];
    const float i1 = 1.f / lsum[1];
    const int r0 = q0 + m0 + (l >> 2);
    const size_t base0 = ((size_t)b * T_ + r0) * C_ + h * D_ + 2 * (l & 3);
    const size_t base1 = base0 + 8 * (size_t)C_;
#pragma unroll
    for (int nt = 0; nt < 8; nt++) {
        uint32_t hi, lo;
        split2(acc[nt][0] * i0, acc[nt][1] * i0, hi, lo);
        *(uint32_t*)&g_chi[base0 + nt * 8] = hi;
        *(uint32_t*)&g_clo[base0 + nt * 8] = lo;
        split2(acc[nt][2] * i1, acc[nt][3] * i1, hi, lo);
        *(uint32_t*)&g_chi[base1 + nt * 8] = hi;
        *(uint32_t*)&g_clo[base1 + nt * 8] = lo;
    }
}

// ---------------------------------------------------------------------------
extern "C" void kernel_launch(void* const* d_in, const int* in_sizes, int n_in,
                              void* d_out, int out_size)
{
    const float* hidden = (const float*)d_in[0];
    const float* qkv_w  = (const float*)d_in[1];
    const float* qkv_b  = (const float*)d_in[2];
    const float* proj_w = (const float*)d_in[3];
    const float* proj_b = (const float*)d_in[4];
    float* out = (float*)d_out;
    (void)in_sizes; (void)n_in; (void)out_size;

    cudaFuncSetAttribute(gemm_mma_kernel<0>,
                         cudaFuncAttributeMaxDynamicSharedMemorySize, GEMM_SMEM);
    cudaFuncSetAttribute(gemm_mma_kernel<1>,
                         cudaFuncAttributeMaxDynamicSharedMemorySize, GEMM_SMEM);
    cudaFuncSetAttribute(attn_mma_kernel,
                         cudaFuncAttributeMaxDynamicSharedMemorySize, ATTN_SMEM);

    // 0) operand conversions
    conv_split_kernel<<<(M_ * C_) / 256, 256>>>(hidden, M_ * C_);
    conv_transpose_kernel<<<dim3(N1_ / 32, C_ / 32), dim3(32, 8)>>>(qkv_w, 0, C_, N1_);
    conv_transpose_kernel<<<dim3(C_ / 32, C_ / 32), dim3(32, 8)>>>(proj_w, 1, C_, C_);

    // 1) QKV projection -> Q/K/V bf16 hi/lo (Q pre-scaled)
    gemm_mma_kernel<0><<<dim3(N1_ / 128, M_ / 128), 512, GEMM_SMEM>>>(qkv_b, nullptr);

    // 2) attention -> ctx bf16 hi/lo
    attn_mma_kernel<<<dim3(T_ / 128, B_ * H_), 256, ATTN_SMEM>>>();

    // 3) output projection
    gemm_mma_kernel<1><<<dim3(C_ / 128, M_ / 128), 512, GEMM_SMEM>>>(proj_b, out);
}

// round 9
// speedup vs baseline: 2.9000x; 1.2249x over previous
#include <cuda_runtime.h>
#include <cuda_fp16.h>
#include <cstdint>
#include <cstddef>

#define B_   8
#define T_   1024
#define C_   768
#define H_   12
#define D_   64
#define M_   (B_ * T_)     /* 8192 */
#define N1_  (3 * C_)      /* 2304 */

// ---------------- device-global scratch -------------------------------------
__device__ __half g_ahi[(size_t)M_ * C_];   // hidden hi/lo
__device__ __half g_alo[(size_t)M_ * C_];
__device__ __half g_chi[(size_t)M_ * C_];   // ctx hi/lo
__device__ __half g_clo[(size_t)M_ * C_];
__device__ __half g_wq_hi[(size_t)N1_ * C_]; // qkv_w^T hi/lo
__device__ __half g_wq_lo[(size_t)N1_ * C_];
__device__ __half g_wp[(size_t)C_ * C_];     // proj_w^T single
// per-head [B*H, T, D]: Q hi/lo (pre-scaled 0.125), K single, V hi/lo
__device__ __half g_qhi[(size_t)M_ * C_];
__device__ __half g_qlo[(size_t)M_ * C_];
__device__ __half g_kh [(size_t)M_ * C_];
__device__ __half g_vhi[(size_t)M_ * C_];
__device__ __half g_vlo[(size_t)M_ * C_];

// ---------------- PTX helpers ----------------------------------------------
__device__ __forceinline__ uint32_t smem_u32(const void* p) {
    uint32_t a;
    asm("{ .reg .u64 t; cvta.to.shared.u64 t, %1; cvt.u32.u64 %0, t; }"
        : "=r"(a) : "l"(p));
    return a;
}

#define CP_ASYNC16(dst, src) \
    asm volatile("cp.async.cg.shared.global [%0], [%1], 16;" \
                 :: "r"(dst), "l"(src) : "memory")
#define CP_COMMIT() asm volatile("cp.async.commit_group;" ::: "memory")
#define CP_WAIT(n)  asm volatile("cp.async.wait_group %0;" :: "n"(n) : "memory")

__device__ __forceinline__ void ldsm4(uint32_t* r, uint32_t a) {
    asm volatile("ldmatrix.sync.aligned.m8n8.x4.shared.b16 {%0,%1,%2,%3}, [%4];"
                 : "=r"(r[0]), "=r"(r[1]), "=r"(r[2]), "=r"(r[3]) : "r"(a));
}
__device__ __forceinline__ void ldsm4t(uint32_t* r, uint32_t a) {
    asm volatile("ldmatrix.sync.aligned.m8n8.x4.trans.shared.b16 {%0,%1,%2,%3}, [%4];"
                 : "=r"(r[0]), "=r"(r[1]), "=r"(r[2]), "=r"(r[3]) : "r"(a));
}

__device__ __forceinline__ void mma_f16(float* c, const uint32_t* a,
                                        uint32_t b0, uint32_t b1) {
    asm volatile(
        "mma.sync.aligned.m16n8k16.row.col.f32.f16.f16.f32 "
        "{%0,%1,%2,%3}, {%4,%5,%6,%7}, {%8,%9}, {%0,%1,%2,%3};"
        : "+f"(c[0]), "+f"(c[1]), "+f"(c[2]), "+f"(c[3])
        : "r"(a[0]), "r"(a[1]), "r"(a[2]), "r"(a[3]), "r"(b0), "r"(b1));
}

__device__ __forceinline__ uint32_t pack_h2(__half x, __half y) {
    __half2 h = __halves2half2(x, y);
    return *(uint32_t*)&h;
}
__device__ __forceinline__ void split2h(float x, float y, uint32_t& hi, uint32_t& lo) {
    __half hx = __float2half_rn(x), hy = __float2half_rn(y);
    __half lx = __float2half_rn(x - __half2float(hx));
    __half ly = __float2half_rn(y - __half2float(hy));
    hi = pack_h2(hx, hy);
    lo = pack_h2(lx, ly);
}

// ---------------- conversion kernels ----------------------------------------
__global__ void conv_split_kernel(const float* __restrict__ src, int n)
{
    int i = blockIdx.x * blockDim.x + threadIdx.x;
    if (i >= n) return;
    float x = src[i];
    __half h = __float2half_rn(x);
    g_ahi[i] = h;
    g_alo[i] = __float2half_rn(x - __half2float(h));
}

// W [K, N] fp32 -> W^T [N, K]. sel 0: qkv_w -> hi/lo. sel 1: proj_w -> single.
__global__ void conv_transpose_kernel(const float* __restrict__ src, int dst_sel,
                                      int K, int N)
{
    __shared__ float tile[32][33];
    int kx = blockIdx.y * 32;
    int nx = blockIdx.x * 32;
    int tx = threadIdx.x;
    int ty = threadIdx.y;
    for (int i = ty; i < 32; i += 8)
        tile[i][tx] = src[(size_t)(kx + i) * N + nx + tx];
    __syncthreads();
    for (int i = ty; i < 32; i += 8) {
        float v = tile[tx][i];
        __half h = __float2half_rn(v);
        size_t o = (size_t)(nx + i) * K + kx + tx;
        if (dst_sel == 0) {
            g_wq_hi[o] = h;
            g_wq_lo[o] = __float2half_rn(v - __half2float(h));
        } else {
            g_wp[o] = h;
        }
    }
}

// ---------------- mma.sync fp16 GEMM ----------------------------------------
// MODE 0: QKV, 3-term (A hi/lo x W hi/lo), 4 tiles/stage; epilogue -> Q/K/V.
// MODE 1: proj, 2-term (ctx hi/lo x W single), 3 tiles/stage; -> out fp32.
#define BKE 32
#define KSB 80
#define TILE_B (128 * KSB)           /* 10240 */
#define NSTG 3
#define NKT 24
#define GEMM_SMEM0 (NSTG * 4 * TILE_B)  /* 122880 */
#define GEMM_SMEM1 (NSTG * 3 * TILE_B)  /* 92160 */

template <int MODE>
__global__ __launch_bounds__(512, 1)
void gemm_mma_kernel(const float* __restrict__ bias, float* __restrict__ out)
{
    constexpr int NTILES = MODE ? 3 : 4;
    constexpr uint32_t STG = (uint32_t)NTILES * TILE_B;

    extern __shared__ char smem[];
    const uint32_t sbase = smem_u32(smem);
    const int tid = threadIdx.x;
    const int wid = tid >> 5;
    const int l   = tid & 31;
    const int gm0 = blockIdx.y * 128;
    const int gn0 = blockIdx.x * 128;

    const int m0 = (wid & 3) * 32;
    const int n0 = (wid >> 2) * 32;

    const int lq = l >> 3, lr = l & 7;
    const uint32_t a_off = (uint32_t)((m0 + (lq & 1) * 8 + lr) * KSB + ((lq >> 1) * 8) * 2);
    const uint32_t b_off = (uint32_t)((n0 + (lq >> 1) * 8 + lr) * KSB + ((lq & 1) * 8) * 2);

    float acc[2][4][4];
#pragma unroll
    for (int mt = 0; mt < 2; mt++)
#pragma unroll
        for (int nt = 0; nt < 4; nt++)
#pragma unroll
            for (int j = 0; j < 4; j++) acc[mt][nt][j] = 0.f;

    const int lrow = tid >> 2;
    const int lch  = tid & 3;
    auto issue_stage = [&](int kt, int s) {
        const int k0 = kt * BKE;
        const uint32_t sb = sbase + (uint32_t)s * STG;
#pragma unroll
        for (int tile = 0; tile < NTILES; tile++) {
            const __half* src = MODE
                ? ((tile == 0) ? g_chi : (tile == 1) ? g_clo : g_wp)
                : ((tile == 0) ? g_ahi : (tile == 1) ? g_alo
                   : (tile == 2) ? g_wq_hi : g_wq_lo);
            const int g0 = (tile < 2) ? gm0 : gn0;
            const void* gp = src + (size_t)(g0 + lrow) * C_ + k0 + lch * 8;
            uint32_t dp = sb + (uint32_t)tile * TILE_B + lrow * KSB + lch * 16;
            CP_ASYNC16(dp, gp);
        }
    };

    issue_stage(0, 0); CP_COMMIT();
    issue_stage(1, 1); CP_COMMIT();

#pragma unroll 1
    for (int kt = 0; kt < NKT; kt++) {
        const int s = kt % NSTG;
        if (kt + 1 < NKT) { CP_WAIT(1); } else { CP_WAIT(0); }
        __syncthreads();
        if (kt + 2 < NKT) {
            issue_stage(kt + 2, (kt + 2) % NSTG);
            CP_COMMIT();
        }

        const uint32_t sb = sbase + (uint32_t)s * STG;
        const uint32_t aHi = sb + a_off;
        const uint32_t aLo = sb + TILE_B + a_off;
        const uint32_t bHi = sb + 2 * TILE_B + b_off;        // MODE1: single W
        const uint32_t bLo = sb + 3 * TILE_B + b_off;        // MODE0 only

#pragma unroll
        for (int kk = 0; kk < 2; kk++) {
            const uint32_t ko = kk * 32;
            uint32_t ah[2][4], al[2][4], bh[2][4], bl[2][4];
#pragma unroll
            for (int mt = 0; mt < 2; mt++) {
                ldsm4(ah[mt], aHi + mt * (16 * KSB) + ko);
                ldsm4(al[mt], aLo + mt * (16 * KSB) + ko);
            }
#pragma unroll
            for (int p = 0; p < 2; p++) {
                ldsm4(bh[p], bHi + p * (16 * KSB) + ko);
                if (MODE == 0) ldsm4(bl[p], bLo + p * (16 * KSB) + ko);
            }
#pragma unroll
            for (int mt = 0; mt < 2; mt++)
#pragma unroll
                for (int nt = 0; nt < 4; nt++) {
                    const int p = nt >> 1, o = (nt & 1) * 2;
                    mma_f16(acc[mt][nt], ah[mt], bh[p][o], bh[p][o + 1]);
                    if (MODE == 0)
                        mma_f16(acc[mt][nt], ah[mt], bl[p][o], bl[p][o + 1]);
                    mma_f16(acc[mt][nt], al[mt], bh[p][o], bh[p][o + 1]);
                }
        }
    }

    // ---------------- epilogue ----------------------------------------------
    const int gr_base = gm0 + m0 + (l >> 2);
    const int gc_loc  = 2 * (l & 3);

    if (MODE == 0) {
        const int which    = gn0 / C_;
        const int rem_base = gn0 - which * C_;
        const float sc = (which == 0) ? 0.125f : 1.0f;
#pragma unroll
        for (int mt = 0; mt < 2; mt++)
#pragma unroll
            for (int nt = 0; nt < 4; nt++) {
                const float* c = acc[mt][nt];
                const int gcn = n0 + nt * 8 + gc_loc;
                const int gc  = gn0 + gcn;
                float2 bb = *(const float2*)&bias[gc];
                const int rem = rem_base + gcn;
                const int h = rem >> 6, d = rem & 63;
#pragma unroll
                for (int hf = 0; hf < 2; hf++) {
                    const int gr = gr_base + mt * 16 + hf * 8;
                    const int b  = gr >> 10, tq = gr & 1023;
                    float x = (c[hf * 2 + 0] + bb.x) * sc;
                    float y = (c[hf * 2 + 1] + bb.y) * sc;
                    size_t idx = (((size_t)(b * H_ + h)) * T_ + tq) * D_ + d;
                    if (which == 1) {
                        *(uint32_t*)&g_kh[idx] =
                            pack_h2(__float2half_rn(x), __float2half_rn(y));
                    } else {
                        uint32_t hi, lo;
                        split2h(x, y, hi, lo);
                        __half* dhi = (which == 0) ? g_qhi : g_vhi;
                        __half* dlo = (which == 0) ? g_qlo : g_vlo;
                        *(uint32_t*)&dhi[idx] = hi;
                        *(uint32_t*)&dlo[idx] = lo;
                    }
                }
            }
    } else {
#pragma unroll
        for (int mt = 0; mt < 2; mt++)
#pragma unroll
            for (int nt = 0; nt < 4; nt++) {
                const float* c = acc[mt][nt];
                const int gc = gn0 + n0 + nt * 8 + gc_loc;
                float2 bb = *(const float2*)&bias[gc];
#pragma unroll
                for (int hf = 0; hf < 2; hf++) {
                    const int gr = gr_base + mt * 16 + hf * 8;
                    float2 o;
                    o.x = c[hf * 2 + 0] + bb.x;
                    o.y = c[hf * 2 + 1] + bb.y;
                    *(float2*)&out[(size_t)gr * C_ + gc] = o;
                }
            }
    }
}

// ---------------- tensor-core flash attention (fp16 2-term) -----------------
// CTA: 128 q-rows x (b,h). 8 warps x 16 rows. 64-key tiles, 16 iters.
// S = (Qhi+Qlo)·K_single : 2 MMAs. O += P_single·(Vhi+Vlo) : 2 MMAs.
#define NT_  16
#define ROWB 144
#define SQ_HI 0
#define SQ_LO 18432
#define SK(s) (36864 + (s) * 9216)    /* K single */
#define SV(s) (55296 + (s) * 18432)   /* vhi +0, vlo +9216 */
#define SP    92160                   /* P single */
#define ATTN_SMEM 110592

__global__ __launch_bounds__(256, 1) void attn_mma_kernel()
{
    extern __shared__ char smem[];
    const uint32_t sbase = smem_u32(smem);
    const int tid = threadIdx.x, wid = tid >> 5, l = tid & 31;
    const int bh = blockIdx.y, q0 = blockIdx.x * 128;
    const size_t hb = (size_t)bh * T_ * D_;
    const __half *Qh = g_qhi + hb, *Ql = g_qlo + hb;
    const __half *Kg = g_kh + hb;
    const __half *Vh = g_vhi + hb, *Vl = g_vlo + hb;

    const int m0 = wid * 16;
    const int lq = l >> 3, lr = l & 7;
    const uint32_t a_off = (uint32_t)((m0 + (lq & 1) * 8 + lr) * ROWB + (lq >> 1) * 16);
    const uint32_t b_off = (uint32_t)(((lq >> 1) * 8 + lr) * ROWB + (lq & 1) * 16);
    const uint32_t v_off = (uint32_t)(((lq & 1) * 8 + lr) * ROWB + (lq >> 1) * 16);

#pragma unroll
    for (int a = 0; a < 2; a++) {
        const __half* src = a ? Ql : Qh;
        const uint32_t dst = sbase + (a ? SQ_LO : SQ_HI);
#pragma unroll
        for (int it = 0; it < 4; it++) {
            int c = it * 256 + tid;
            int row = c >> 3, ch = c & 7;
            CP_ASYNC16(dst + row * ROWB + ch * 16,
                       src + (size_t)(q0 + row) * D_ + ch * 8);
        }
    }
    auto load_kv = [&](int kt, int s) {
        const int r0 = kt * 64;
#pragma unroll
        for (int a = 0; a < 3; a++) {
            const __half* src = (a == 0) ? Kg : (a == 1) ? Vh : Vl;
            const uint32_t dst = sbase + ((a == 0) ? SK(s) : SV(s) + (a - 1) * 9216);
#pragma unroll
            for (int it = 0; it < 2; it++) {
                int c = it * 256 + tid;
                int row = c >> 3, ch = c & 7;
                CP_ASYNC16(dst + row * ROWB + ch * 16,
                           src + (size_t)(r0 + row) * D_ + ch * 8);
            }
        }
    };
    load_kv(0, 0);
    CP_COMMIT();
    CP_WAIT(0);
    __syncthreads();

    uint32_t qh[4][4], ql[4][4];
#pragma unroll
    for (int kk = 0; kk < 4; kk++) {
        ldsm4(qh[kk], sbase + SQ_HI + a_off + kk * 32);
        ldsm4(ql[kk], sbase + SQ_LO + a_off + kk * 32);
    }

    float mrow[2] = {-1e30f, -1e30f}, lsum[2] = {0.f, 0.f};
    float acc[8][4];
#pragma unroll
    for (int nt = 0; nt < 8; nt++)
#pragma unroll
        for (int j = 0; j < 4; j++) acc[nt][j] = 0.f;

    const uint32_t prow0 = (uint32_t)((m0 + (l >> 2)) * ROWB + (l & 3) * 4);

    for (int kt = 0; kt < NT_; kt++) {
        const int s = kt & 1;
        __syncthreads();
        if (kt + 1 < NT_) {
            load_kv(kt + 1, s ^ 1);
            CP_COMMIT();
            CP_WAIT(1);
        } else {
            CP_WAIT(0);
        }
        __syncthreads();

        // ---- S = Q K^T ----
        float sc[8][4];
#pragma unroll
        for (int nt = 0; nt < 8; nt++)
#pragma unroll
            for (int j = 0; j < 4; j++) sc[nt][j] = 0.f;

        const uint32_t kb = sbase + SK(s) + b_off;
#pragma unroll
        for (int kk = 0; kk < 4; kk++) {
            uint32_t b4[4][4];
#pragma unroll
            for (int p = 0; p < 4; p++)
                ldsm4(b4[p], kb + p * (16 * ROWB) + kk * 32);
#pragma unroll
            for (int nt = 0; nt < 8; nt++) {
                const int p = nt >> 1, o = (nt & 1) * 2;
                mma_f16(sc[nt], qh[kk], b4[p][o], b4[p][o + 1]);
                mma_f16(sc[nt], ql[kk], b4[p][o], b4[p][o + 1]);
            }
        }

        // ---- online softmax ----
        float mx0 = sc[0][0], mx1 = sc[0][2];
#pragma unroll
        for (int nt = 0; nt < 8; nt++) {
            mx0 = fmaxf(mx0, fmaxf(sc[nt][0], sc[nt][1]));
            mx1 = fmaxf(mx1, fmaxf(sc[nt][2], sc[nt][3]));
        }
        mx0 = fmaxf(mx0, __shfl_xor_sync(0xffffffffu, mx0, 1));
        mx0 = fmaxf(mx0, __shfl_xor_sync(0xffffffffu, mx0, 2));
        mx1 = fmaxf(mx1, __shfl_xor_sync(0xffffffffu, mx1, 1));
        mx1 = fmaxf(mx1, __shfl_xor_sync(0xffffffffu, mx1, 2));
        const float mn0 = fmaxf(mrow[0], mx0);
        const float mn1 = fmaxf(mrow[1], mx1);
        const float f0 = __expf(mrow[0] - mn0);
        const float f1 = __expf(mrow[1] - mn1);
        mrow[0] = mn0; mrow[1] = mn1;

        float rs0 = 0.f, rs1 = 0.f;
#pragma unroll
        for (int nt = 0; nt < 8; nt++) {
            float p0 = __expf(sc[nt][0] - mn0);
            float p1 = __expf(sc[nt][1] - mn0);
            float p2 = __expf(sc[nt][2] - mn1);
            float p3 = __expf(sc[nt][3] - mn1);
            rs0 += p0 + p1; rs1 += p2 + p3;
            const uint32_t o0 = prow0 + nt * 16;
            *(uint32_t*)(smem + SP + o0) =
                pack_h2(__float2half_rn(p0), __float2half_rn(p1));
            *(uint32_t*)(smem + SP + o0 + 8 * ROWB) =
                pack_h2(__float2half_rn(p2), __float2half_rn(p3));
            acc[nt][0] *= f0; acc[nt][1] *= f0;
            acc[nt][2] *= f1; acc[nt][3] *= f1;
        }
        rs0 += __shfl_xor_sync(0xffffffffu, rs0, 1);
        rs0 += __shfl_xor_sync(0xffffffffu, rs0, 2);
        rs1 += __shfl_xor_sync(0xffffffffu, rs1, 1);
        rs1 += __shfl_xor_sync(0xffffffffu, rs1, 2);
        lsum[0] = lsum[0] * f0 + rs0;
        lsum[1] = lsum[1] * f1 + rs1;
        __syncwarp();

        // ---- O += P V ----
        const uint32_t pb  = sbase + SP + a_off;
        const uint32_t vbh = sbase + SV(s) + v_off;
        const uint32_t vbl = vbh + 9216;
#pragma unroll
        for (int kk = 0; kk < 4; kk++) {
            uint32_t ph[4];
            ldsm4(ph, pb + kk * 32);
            uint32_t vh4[4][4], vl4[4][4];
#pragma unroll
            for (int p = 0; p < 4; p++) {
                ldsm4t(vh4[p], vbh + kk * (16 * ROWB) + p * 32);
                ldsm4t(vl4[p], vbl + kk * (16 * ROWB) + p * 32);
            }
#pragma unroll
            for (int nt = 0; nt < 8; nt++) {
                const int p = nt >> 1, o = (nt & 1) * 2;
                mma_f16(acc[nt], ph, vh4[p][o], vh4[p][o + 1]);
                mma_f16(acc[nt], ph, vl4[p][o], vl4[p][o + 1]);
            }
        }
    }

    // ---- epilogue: ctx -> fp16 hi/lo [B*T, C] ----
    const int b = bh / H_, h = bh - b * H_;
    const float i0 = 1.f / lsum[0];
    const float i1 = 1.f / lsum[1];
    const int r0 = q0 + m0 + (l >> 2);
    const size_t base0 = ((size_t)b * T_ + r0) * C_ + h * D_ + 2 * (l & 3);
    const size_t base1 = base0 + 8 * (size_t)C_;
#pragma unroll
    for (int nt = 0; nt < 8; nt++) {
        uint32_t hi, lo;
        split2h(acc[nt][0] * i0, acc[nt][1] * i0, hi, lo);
        *(uint32_t*)&g_chi[base0 + nt * 8] = hi;
        *(uint32_t*)&g_clo[base0 + nt * 8] = lo;
        split2h(acc[nt][2] * i1, acc[nt][3] * i1, hi, lo);
        *(uint32_t*)&g_chi[base1 + nt * 8] = hi;
        *(uint32_t*)&g_clo[base1 + nt * 8] = lo;
    }
}

// ---------------------------------------------------------------------------
extern "C" void kernel_launch(void* const* d_in, const int* in_sizes, int n_in,
                              void* d_out, int out_size)
{
    const float* hidden = (const float*)d_in[0];
    const float* qkv_w  = (const float*)d_in[1];
    const float* qkv_b  = (const float*)d_in[2];
    const float* proj_w = (const float*)d_in[3];
    const float* proj_b = (const float*)d_in[4];
    float* out = (float*)d_out;
    (void)in_sizes; (void)n_in; (void)out_size;

    cudaFuncSetAttribute(gemm_mma_kernel<0>,
                         cudaFuncAttributeMaxDynamicSharedMemorySize, GEMM_SMEM0);
    cudaFuncSetAttribute(gemm_mma_kernel<1>,
                         cudaFuncAttributeMaxDynamicSharedMemorySize, GEMM_SMEM1);
    cudaFuncSetAttribute(attn_mma_kernel,
                         cudaFuncAttributeMaxDynamicSharedMemorySize, ATTN_SMEM);

    // 0) operand conversions
    conv_split_kernel<<<(M_ * C_) / 256, 256>>>(hidden, M_ * C_);
    conv_transpose_kernel<<<dim3(N1_ / 32, C_ / 32), dim3(32, 8)>>>(qkv_w, 0, C_, N1_);
    conv_transpose_kernel<<<dim3(C_ / 32, C_ / 32), dim3(32, 8)>>>(proj_w, 1, C_, C_);

    // 1) QKV projection (3-term fp16) -> Q hi/lo, K single, V hi/lo
    gemm_mma_kernel<0><<<dim3(N1_ / 128, M_ / 128), 512, GEMM_SMEM0>>>(qkv_b, nullptr);

    // 2) attention (2-term fp16) -> ctx hi/lo
    attn_mma_kernel<<<dim3(T_ / 128, B_ * H_), 256, ATTN_SMEM>>>();

    // 3) output projection (2-term fp16)
    gemm_mma_kernel<1><<<dim3(C_ / 128, M_ / 128), 512, GEMM_SMEM1>>>(proj_b, out);
}

// round 11
// speedup vs baseline: 4.8532x; 1.6735x over previous
#include <cuda_runtime.h>
#include <cuda_fp16.h>
#include <cstdint>
#include <cstddef>

#define B_   8
#define T_   1024
#define C_   768
#define H_   12
#define D_   64
#define M_   (B_ * T_)     /* 8192 */
#define N1_  (3 * C_)      /* 2304 */

// ---------------- device-global scratch (all fp16 single) -------------------
__device__ __half g_a [(size_t)M_ * C_];     // hidden
__device__ __half g_c [(size_t)M_ * C_];     // ctx
__device__ __half g_wq[(size_t)N1_ * C_];    // qkv_w^T [2304,768]
__device__ __half g_wp[(size_t)C_ * C_];     // proj_w^T [768,768]
__device__ __half g_q [(size_t)M_ * C_];     // [B*H,T,D], pre-scaled 0.125
__device__ __half g_k [(size_t)M_ * C_];
__device__ __half g_v [(size_t)M_ * C_];

// ---------------- PTX helpers ----------------------------------------------
__device__ __forceinline__ uint32_t smem_u32(const void* p) {
    uint32_t a;
    asm("{ .reg .u64 t; cvta.to.shared.u64 t, %1; cvt.u32.u64 %0, t; }"
        : "=r"(a) : "l"(p));
    return a;
}

#define CP_ASYNC16(dst, src) \
    asm volatile("cp.async.cg.shared.global [%0], [%1], 16;" \
                 :: "r"(dst), "l"(src) : "memory")
#define CP_COMMIT() asm volatile("cp.async.commit_group;" ::: "memory")
#define CP_WAIT(n)  asm volatile("cp.async.wait_group %0;" :: "n"(n) : "memory")

__device__ __forceinline__ void ldsm4(uint32_t* r, uint32_t a) {
    asm volatile("ldmatrix.sync.aligned.m8n8.x4.shared.b16 {%0,%1,%2,%3}, [%4];"
                 : "=r"(r[0]), "=r"(r[1]), "=r"(r[2]), "=r"(r[3]) : "r"(a));
}
__device__ __forceinline__ void ldsm4t(uint32_t* r, uint32_t a) {
    asm volatile("ldmatrix.sync.aligned.m8n8.x4.trans.shared.b16 {%0,%1,%2,%3}, [%4];"
                 : "=r"(r[0]), "=r"(r[1]), "=r"(r[2]), "=r"(r[3]) : "r"(a));
}

__device__ __forceinline__ void mma_f16(float* c, const uint32_t* a,
                                        uint32_t b0, uint32_t b1) {
    asm volatile(
        "mma.sync.aligned.m16n8k16.row.col.f32.f16.f16.f32 "
        "{%0,%1,%2,%3}, {%4,%5,%6,%7}, {%8,%9}, {%0,%1,%2,%3};"
        : "+f"(c[0]), "+f"(c[1]), "+f"(c[2]), "+f"(c[3])
        : "r"(a[0]), "r"(a[1]), "r"(a[2]), "r"(a[3]), "r"(b0), "r"(b1));
}

__device__ __forceinline__ uint32_t pack_h2(float x, float y) {
    __half2 h = __halves2half2(__float2half_rn(x), __float2half_rn(y));
    return *(uint32_t*)&h;
}

// ---------------- conversion kernels ----------------------------------------
__global__ void conv_h_kernel(const float* __restrict__ src, int n)
{
    int i = blockIdx.x * blockDim.x + threadIdx.x;
    if (i >= n) return;
    g_a[i] = __float2half_rn(src[i]);
}

// W [K, N] fp32 -> W^T [N, K] fp16. sel 0: qkv_w, 1: proj_w
__global__ void conv_transpose_kernel(const float* __restrict__ src, int dst_sel,
                                      int K, int N)
{
    __shared__ float tile[32][33];
    int kx = blockIdx.y * 32;
    int nx = blockIdx.x * 32;
    int tx = threadIdx.x;
    int ty = threadIdx.y;
    for (int i = ty; i < 32; i += 8)
        tile[i][tx] = src[(size_t)(kx + i) * N + nx + tx];
    __syncthreads();
    __half* dst = dst_sel ? g_wp : g_wq;
    for (int i = ty; i < 32; i += 8)
        dst[(size_t)(nx + i) * K + kx + tx] = __float2half_rn(tile[tx][i]);
}

// ---------------- mma.sync fp16 GEMM ----------------------------------------
// C[M,N] = A[M,768] @ W^T + bias.  128x128 CTA, 512 thr, warp 32x32, 3-stage.
#define BKE 32
#define KSB 80
#define TILE_B (128 * KSB)           /* 10240 */
#define NSTG 3
#define NKT 24
#define STG_B (2 * TILE_B)           /* A + W */
#define GEMM_SMEM (NSTG * STG_B)     /* 61440 */

template <int MODE>
__global__ __launch_bounds__(512, 1)
void gemm_mma_kernel(const float* __restrict__ bias, float* __restrict__ out)
{
    extern __shared__ char smem[];
    const uint32_t sbase = smem_u32(smem);
    const int tid = threadIdx.x;
    const int wid = tid >> 5;
    const int l   = tid & 31;
    const int gm0 = blockIdx.y * 128;
    const int gn0 = blockIdx.x * 128;

    const __half* gA = MODE ? g_c  : g_a;
    const __half* gB = MODE ? g_wp : g_wq;

    const int m0 = (wid & 3) * 32;
    const int n0 = (wid >> 2) * 32;

    const int lq = l >> 3, lr = l & 7;
    const uint32_t a_off = (uint32_t)((m0 + (lq & 1) * 8 + lr) * KSB + ((lq >> 1) * 8) * 2);
    const uint32_t b_off = (uint32_t)((n0 + (lq >> 1) * 8 + lr) * KSB + ((lq & 1) * 8) * 2);

    float acc[2][4][4];
#pragma unroll
    for (int mt = 0; mt < 2; mt++)
#pragma unroll
        for (int nt = 0; nt < 4; nt++)
#pragma unroll
            for (int j = 0; j < 4; j++) acc[mt][nt][j] = 0.f;

    const int lrow = tid >> 2;
    const int lch  = tid & 3;
    auto issue_stage = [&](int kt, int s) {
        const int k0 = kt * BKE;
        const uint32_t sb = sbase + (uint32_t)s * STG_B;
        CP_ASYNC16(sb + lrow * KSB + lch * 16,
                   gA + (size_t)(gm0 + lrow) * C_ + k0 + lch * 8);
        CP_ASYNC16(sb + TILE_B + lrow * KSB + lch * 16,
                   gB + (size_t)(gn0 + lrow) * C_ + k0 + lch * 8);
    };

    issue_stage(0, 0); CP_COMMIT();
    issue_stage(1, 1); CP_COMMIT();

#pragma unroll 1
    for (int kt = 0; kt < NKT; kt++) {
        const int s = kt % NSTG;
        if (kt + 1 < NKT) { CP_WAIT(1); } else { CP_WAIT(0); }
        __syncthreads();
        if (kt + 2 < NKT) {
            issue_stage(kt + 2, (kt + 2) % NSTG);
            CP_COMMIT();
        }

        const uint32_t sb = sbase + (uint32_t)s * STG_B;
        const uint32_t aP = sb + a_off;
        const uint32_t bP = sb + TILE_B + b_off;

#pragma unroll
        for (int kk = 0; kk < 2; kk++) {
            const uint32_t ko = kk * 32;
            uint32_t ar[2][4], br[2][4];
#pragma unroll
            for (int mt = 0; mt < 2; mt++)
                ldsm4(ar[mt], aP + mt * (16 * KSB) + ko);
#pragma unroll
            for (int p = 0; p < 2; p++)
                ldsm4(br[p], bP + p * (16 * KSB) + ko);
#pragma unroll
            for (int mt = 0; mt < 2; mt++)
#pragma unroll
                for (int nt = 0; nt < 4; nt++) {
                    const int p = nt >> 1, o = (nt & 1) * 2;
                    mma_f16(acc[mt][nt], ar[mt], br[p][o], br[p][o + 1]);
                }
        }
    }

    // ---------------- epilogue ----------------------------------------------
    const int gr_base = gm0 + m0 + (l >> 2);
    const int gc_loc  = 2 * (l & 3);

    if (MODE == 0) {
        const int which    = gn0 / C_;
        const int rem_base = gn0 - which * C_;
        __half* dst = (which == 0) ? g_q : (which == 1) ? g_k : g_v;
        const float sc = (which == 0) ? 0.125f : 1.0f;
#pragma unroll
        for (int mt = 0; mt < 2; mt++)
#pragma unroll
            for (int nt = 0; nt < 4; nt++) {
                const float* c = acc[mt][nt];
                const int gcn = n0 + nt * 8 + gc_loc;
                const int gc  = gn0 + gcn;
                float2 bb = *(const float2*)&bias[gc];
                const int rem = rem_base + gcn;
                const int h = rem >> 6, d = rem & 63;
#pragma unroll
                for (int hf = 0; hf < 2; hf++) {
                    const int gr = gr_base + mt * 16 + hf * 8;
                    const int b  = gr >> 10, tq = gr & 1023;
                    size_t idx = (((size_t)(b * H_ + h)) * T_ + tq) * D_ + d;
                    *(uint32_t*)&dst[idx] = pack_h2((c[hf * 2 + 0] + bb.x) * sc,
                                                    (c[hf * 2 + 1] + bb.y) * sc);
                }
            }
    } else {
#pragma unroll
        for (int mt = 0; mt < 2; mt++)
#pragma unroll
            for (int nt = 0; nt < 4; nt++) {
                const float* c = acc[mt][nt];
                const int gc = gn0 + n0 + nt * 8 + gc_loc;
                float2 bb = *(const float2*)&bias[gc];
#pragma unroll
                for (int hf = 0; hf < 2; hf++) {
                    const int gr = gr_base + mt * 16 + hf * 8;
                    float2 o;
                    o.x = c[hf * 2 + 0] + bb.x;
                    o.y = c[hf * 2 + 1] + bb.y;
                    *(float2*)&out[(size_t)gr * C_ + gc] = o;
                }
            }
    }
}

// ---------------- tensor-core flash attention (fp16 single) -----------------
// CTA: 128 q-rows x (b,h). 8 warps x 16 rows. 64-key tiles, 16 iters.
#define NT_  16
#define ROWB 144
#define SQ    0                       /* 18432 */
#define SK(s) (18432 + (s) * 9216)
#define SV(s) (36864 + (s) * 9216)
#define SP    55296                   /* 18432 */
#define ATTN_SMEM 73728

__global__ __launch_bounds__(256, 1) void attn_mma_kernel()
{
    extern __shared__ char smem[];
    const uint32_t sbase = smem_u32(smem);
    const int tid = threadIdx.x, wid = tid >> 5, l = tid & 31;
    const int bh = blockIdx.y, q0 = blockIdx.x * 128;
    const size_t hb = (size_t)bh * T_ * D_;
    const __half *Qg = g_q + hb, *Kg = g_k + hb, *Vg = g_v + hb;

    const int m0 = wid * 16;
    const int lq = l >> 3, lr = l & 7;
    const uint32_t a_off = (uint32_t)((m0 + (lq & 1) * 8 + lr) * ROWB + (lq >> 1) * 16);
    const uint32_t b_off = (uint32_t)(((lq >> 1) * 8 + lr) * ROWB + (lq & 1) * 16);
    const uint32_t v_off = (uint32_t)(((lq & 1) * 8 + lr) * ROWB + (lq >> 1) * 16);

    // Q tile: 128 rows x 8 chunks
#pragma unroll
    for (int it = 0; it < 4; it++) {
        int c = it * 256 + tid;
        int row = c >> 3, ch = c & 7;
        CP_ASYNC16(sbase + SQ + row * ROWB + ch * 16,
                   Qg + (size_t)(q0 + row) * D_ + ch * 8);
    }
    auto load_kv = [&](int kt, int s) {
        const int r0 = kt * 64;
#pragma unroll
        for (int a = 0; a < 2; a++) {
            const __half* src = a ? Vg : Kg;
            const uint32_t dst = sbase + (a ? SV(s) : SK(s));
#pragma unroll
            for (int it = 0; it < 2; it++) {
                int c = it * 256 + tid;
                int row = c >> 3, ch = c & 7;
                CP_ASYNC16(dst + row * ROWB + ch * 16,
                           src + (size_t)(r0 + row) * D_ + ch * 8);
            }
        }
    };
    load_kv(0, 0);
    CP_COMMIT();
    CP_WAIT(0);
    __syncthreads();

    uint32_t qf[4][4];
#pragma unroll
    for (int kk = 0; kk < 4; kk++)
        ldsm4(qf[kk], sbase + SQ + a_off + kk * 32);

    float mrow[2] = {-1e30f, -1e30f}, lsum[2] = {0.f, 0.f};
    float acc[8][4];
#pragma unroll
    for (int nt = 0; nt < 8; nt++)
#pragma unroll
        for (int j = 0; j < 4; j++) acc[nt][j] = 0.f;

    const uint32_t prow0 = (uint32_t)((m0 + (l >> 2)) * ROWB + (l & 3) * 4);

    for (int kt = 0; kt < NT_; kt++) {
        const int s = kt & 1;
        __syncthreads();
        if (kt + 1 < NT_) {
            load_kv(kt + 1, s ^ 1);
            CP_COMMIT();
            CP_WAIT(1);
        } else {
            CP_WAIT(0);
        }
        __syncthreads();

        // ---- S = Q K^T ----
        float sc[8][4];
#pragma unroll
        for (int nt = 0; nt < 8; nt++)
#pragma unroll
            for (int j = 0; j < 4; j++) sc[nt][j] = 0.f;

        const uint32_t kb = sbase + SK(s) + b_off;
#pragma unroll
        for (int kk = 0; kk < 4; kk++) {
            uint32_t b4[4][4];
#pragma unroll
            for (int p = 0; p < 4; p++)
                ldsm4(b4[p], kb + p * (16 * ROWB) + kk * 32);
#pragma unroll
            for (int nt = 0; nt < 8; nt++) {
                const int p = nt >> 1, o = (nt & 1) * 2;
                mma_f16(sc[nt], qf[kk], b4[p][o], b4[p][o + 1]);
            }
        }

        // ---- online softmax ----
        float mx0 = sc[0][0], mx1 = sc[0][2];
#pragma unroll
        for (int nt = 0; nt < 8; nt++) {
            mx0 = fmaxf(mx0, fmaxf(sc[nt][0], sc[nt][1]));
            mx1 = fmaxf(mx1, fmaxf(sc[nt][2], sc[nt][3]));
        }
        mx0 = fmaxf(mx0, __shfl_xor_sync(0xffffffffu, mx0, 1));
        mx0 = fmaxf(mx0, __shfl_xor_sync(0xffffffffu, mx0, 2));
        mx1 = fmaxf(mx1, __shfl_xor_sync(0xffffffffu, mx1, 1));
        mx1 = fmaxf(mx1, __shfl_xor_sync(0xffffffffu, mx1, 2));
        const float mn0 = fmaxf(mrow[0], mx0);
        const float mn1 = fmaxf(mrow[1], mx1);
        const float f0 = __expf(mrow[0] - mn0);
        const float f1 = __expf(mrow[1] - mn1);
        mrow[0] = mn0; mrow[1] = mn1;

        float rs0 = 0.f, rs1 = 0.f;
#pragma unroll
        for (int nt = 0; nt < 8; nt++) {
            float p0 = __expf(sc[nt][0] - mn0);
            float p1 = __expf(sc[nt][1] - mn0);
            float p2 = __expf(sc[nt][2] - mn1);
            float p3 = __expf(sc[nt][3] - mn1);
            rs0 += p0 + p1; rs1 += p2 + p3;
            const uint32_t o0 = prow0 + nt * 16;
            *(uint32_t*)(smem + SP + o0) = pack_h2(p0, p1);
            *(uint32_t*)(smem + SP + o0 + 8 * ROWB) = pack_h2(p2, p3);
            acc[nt][0] *= f0; acc[nt][1] *= f0;
            acc[nt][2] *= f1; acc[nt][3] *= f1;
        }
        rs0 += __shfl_xor_sync(0xffffffffu, rs0, 1);
        rs0 += __shfl_xor_sync(0xffffffffu, rs0, 2);
        rs1 += __shfl_xor_sync(0xffffffffu, rs1, 1);
        rs1 += __shfl_xor_sync(0xffffffffu, rs1, 2);
        lsum[0] = lsum[0] * f0 + rs0;
        lsum[1] = lsum[1] * f1 + rs1;
        __syncwarp();

        // ---- O += P V ----
        const uint32_t pb = sbase + SP + a_off;
        const uint32_t vb = sbase + SV(s) + v_off;
#pragma unroll
        for (int kk = 0; kk < 4; kk++) {
            uint32_t pf[4];
            ldsm4(pf, pb + kk * 32);
            uint32_t v4[4][4];
#pragma unroll
            for (int p = 0; p < 4; p++)
                ldsm4t(v4[p], vb + kk * (16 * ROWB) + p * 32);
#pragma unroll
            for (int nt = 0; nt < 8; nt++) {
                const int p = nt >> 1, o = (nt & 1) * 2;
                mma_f16(acc[nt], pf, v4[p][o], v4[p][o + 1]);
            }
        }
    }

    // ---- epilogue: ctx -> fp16 [B*T, C] ----
    const int b = bh / H_, h = bh - b * H_;
    const float i0 = 1.f / lsum[0];
    const float i1 = 1.f / lsum[1];
    const int r0 = q0 + m0 + (l >> 2);
    const size_t base0 = ((size_t)b * T_ + r0) * C_ + h * D_ + 2 * (l & 3);
    const size_t base1 = base0 + 8 * (size_t)C_;
#pragma unroll
    for (int nt = 0; nt < 8; nt++) {
        *(uint32_t*)&g_c[base0 + nt * 8] = pack_h2(acc[nt][0] * i0, acc[nt][1] * i0);
        *(uint32_t*)&g_c[base1 + nt * 8] = pack_h2(acc[nt][2] * i1, acc[nt][3] * i1);
    }
}

// ---------------------------------------------------------------------------
extern "C" void kernel_launch(void* const* d_in, const int* in_sizes, int n_in,
                              void* d_out, int out_size)
{
    const float* hidden = (const float*)d_in[0];
    const float* qkv_w  = (const float*)d_in[1];
    const float* qkv_b  = (const float*)d_in[2];
    const float* proj_w = (const float*)d_in[3];
    const float* proj_b = (const float*)d_in[4];
    float* out = (float*)d_out;
    (void)in_sizes; (void)n_in; (void)out_size;

    cudaFuncSetAttribute(gemm_mma_kernel<0>,
                         cudaFuncAttributeMaxDynamicSharedMemorySize, GEMM_SMEM);
    cudaFuncSetAttribute(gemm_mma_kernel<1>,
                         cudaFuncAttributeMaxDynamicSharedMemorySize, GEMM_SMEM);
    cudaFuncSetAttribute(attn_mma_kernel,
                         cudaFuncAttributeMaxDynamicSharedMemorySize, ATTN_SMEM);

    // 0) operand conversions
    conv_h_kernel<<<(M_ * C_) / 256, 256>>>(hidden, M_ * C_);
    conv_transpose_kernel<<<dim3(N1_ / 32, C_ / 32), dim3(32, 8)>>>(qkv_w, 0, C_, N1_);
    conv_transpose_kernel<<<dim3(C_ / 32, C_ / 32), dim3(32, 8)>>>(proj_w, 1, C_, C_);

    // 1) QKV projection -> Q (pre-scaled) / K / V fp16
    gemm_mma_kernel<0><<<dim3(N1_ / 128, M_ / 128), 512, GEMM_SMEM>>>(qkv_b, nullptr);

    // 2) attention -> ctx fp16
    attn_mma_kernel<<<dim3(T_ / 128, B_ * H_), 256, ATTN_SMEM>>>();

    // 3) output projection -> out fp32
    gemm_mma_kernel<1><<<dim3(C_ / 128, M_ / 128), 512, GEMM_SMEM>>>(proj_b, out);
}

// round 12
// speedup vs baseline: 5.1184x; 1.0546x over previous
#include <cuda_runtime.h>
#include <cuda_fp16.h>
#include <cstdint>
#include <cstddef>

#define B_   8
#define T_   1024
#define C_   768
#define H_   12
#define D_   64
#define M_   (B_ * T_)     /* 8192 */
#define N1_  (3 * C_)      /* 2304 */

// ---------------- device-global scratch (all fp16 single) -------------------
__device__ __half g_a [(size_t)M_ * C_];     // hidden
__device__ __half g_c [(size_t)M_ * C_];     // ctx
__device__ __half g_wq[(size_t)N1_ * C_];    // qkv_w^T [2304,768]
__device__ __half g_wp[(size_t)C_ * C_];     // proj_w^T [768,768]
__device__ __half g_q [(size_t)M_ * C_];     // [B*H,T,D], pre-scaled 0.125
__device__ __half g_k [(size_t)M_ * C_];
__device__ __half g_v [(size_t)M_ * C_];

// ---------------- PTX helpers ----------------------------------------------
__device__ __forceinline__ uint32_t smem_u32(const void* p) {
    uint32_t a;
    asm("{ .reg .u64 t; cvta.to.shared.u64 t, %1; cvt.u32.u64 %0, t; }"
        : "=r"(a) : "l"(p));
    return a;
}

#define CP_ASYNC16(dst, src) \
    asm volatile("cp.async.cg.shared.global [%0], [%1], 16;" \
                 :: "r"(dst), "l"(src) : "memory")
#define CP_COMMIT() asm volatile("cp.async.commit_group;" ::: "memory")
#define CP_WAIT(n)  asm volatile("cp.async.wait_group %0;" :: "n"(n) : "memory")

__device__ __forceinline__ void ldsm4(uint32_t* r, uint32_t a) {
    asm volatile("ldmatrix.sync.aligned.m8n8.x4.shared.b16 {%0,%1,%2,%3}, [%4];"
                 : "=r"(r[0]), "=r"(r[1]), "=r"(r[2]), "=r"(r[3]) : "r"(a));
}
__device__ __forceinline__ void ldsm4t(uint32_t* r, uint32_t a) {
    asm volatile("ldmatrix.sync.aligned.m8n8.x4.trans.shared.b16 {%0,%1,%2,%3}, [%4];"
                 : "=r"(r[0]), "=r"(r[1]), "=r"(r[2]), "=r"(r[3]) : "r"(a));
}

__device__ __forceinline__ void mma_f16(float* c, const uint32_t* a,
                                        uint32_t b0, uint32_t b1) {
    asm volatile(
        "mma.sync.aligned.m16n8k16.row.col.f32.f16.f16.f32 "
        "{%0,%1,%2,%3}, {%4,%5,%6,%7}, {%8,%9}, {%0,%1,%2,%3};"
        : "+f"(c[0]), "+f"(c[1]), "+f"(c[2]), "+f"(c[3])
        : "r"(a[0]), "r"(a[1]), "r"(a[2]), "r"(a[3]), "r"(b0), "r"(b1));
}

__device__ __forceinline__ uint32_t pack_h2(float x, float y) {
    __half2 h = __halves2half2(__float2half_rn(x), __float2half_rn(y));
    return *(uint32_t*)&h;
}

// ---------------- conversion kernels ----------------------------------------
__global__ void conv_h_kernel(const float* __restrict__ src, int n)
{
    int i = blockIdx.x * blockDim.x + threadIdx.x;
    if (i >= n) return;
    g_a[i] = __float2half_rn(src[i]);
}

// W [K, N] fp32 -> W^T [N, K] fp16. sel 0: qkv_w, 1: proj_w
__global__ void conv_transpose_kernel(const float* __restrict__ src, int dst_sel,
                                      int K, int N)
{
    __shared__ float tile[32][33];
    int kx = blockIdx.y * 32;
    int nx = blockIdx.x * 32;
    int tx = threadIdx.x;
    int ty = threadIdx.y;
    for (int i = ty; i < 32; i += 8)
        tile[i][tx] = src[(size_t)(kx + i) * N + nx + tx];
    __syncthreads();
    __half* dst = dst_sel ? g_wp : g_wq;
    for (int i = ty; i < 32; i += 8)
        dst[(size_t)(nx + i) * K + kx + tx] = __float2half_rn(tile[tx][i]);
}

// ---------------- mma.sync fp16 GEMM ----------------------------------------
// MODE 0: QKV. CTA 128x256, 16 warps 4x4, warp 32x64. grid 9x64.
// MODE 1: proj. CTA 128x128, 16 warps 4x4, warp 32x32. grid 6x64.
#define BKE 32
#define KSB 80
#define TILE_A (128 * KSB)           /* 10240 */
#define NSTG 3
#define NKT 24

template <int MODE>
__global__ __launch_bounds__(512, 1)
void gemm_mma_kernel(const float* __restrict__ bias, float* __restrict__ out)
{
    constexpr int BN   = MODE ? 128 : 256;        // CTA n-width
    constexpr int WN   = BN / 4;                  // warp n-width (64 | 32)
    constexpr int NTW  = WN / 8;                  // 8x8 n-tiles per warp (8 | 4)
    constexpr int NP   = NTW / 2;                 // b-ldsm4 per kk (4 | 2)
    constexpr uint32_t TILE_B_SZ = (uint32_t)BN * KSB;
    constexpr uint32_t STG_B = TILE_A + TILE_B_SZ;
    constexpr int NCHUNK = (128 + BN) * 4;        // 16B chunks per stage

    extern __shared__ char smem[];
    const uint32_t sbase = smem_u32(smem);
    const int tid = threadIdx.x;
    const int wid = tid >> 5;
    const int l   = tid & 31;
    const int gm0 = blockIdx.y * 128;
    const int gn0 = blockIdx.x * BN;

    const __half* gA = MODE ? g_c  : g_a;
    const __half* gB = MODE ? g_wp : g_wq;

    const int m0 = (wid & 3) * 32;
    const int n0 = (wid >> 2) * WN;

    const int lq = l >> 3, lr = l & 7;
    const uint32_t a_off = (uint32_t)((m0 + (lq & 1) * 8 + lr) * KSB + ((lq >> 1) * 8) * 2);
    const uint32_t b_off = (uint32_t)((n0 + (lq >> 1) * 8 + lr) * KSB + ((lq & 1) * 8) * 2);

    float acc[2][NTW][4];
#pragma unroll
    for (int mt = 0; mt < 2; mt++)
#pragma unroll
        for (int nt = 0; nt < NTW; nt++)
#pragma unroll
            for (int j = 0; j < 4; j++) acc[mt][nt][j] = 0.f;

    auto issue_stage = [&](int kt, int s) {
        const int k0 = kt * BKE;
        const uint32_t sb = sbase + (uint32_t)s * STG_B;
#pragma unroll
        for (int c = tid; c < NCHUNK; c += 512) {
            const int row = c >> 2, ch = c & 3;
            const __half* src;
            int grow;
            uint32_t doff;
            if (row < 128) { src = gA; grow = gm0 + row; doff = (uint32_t)row * KSB; }
            else { src = gB; grow = gn0 + (row - 128); doff = TILE_A + (uint32_t)(row - 128) * KSB; }
            CP_ASYNC16(sb + doff + ch * 16, src + (size_t)grow * C_ + k0 + ch * 8);
        }
    };

    issue_stage(0, 0); CP_COMMIT();
    issue_stage(1, 1); CP_COMMIT();

#pragma unroll 1
    for (int kt = 0; kt < NKT; kt++) {
        const int s = kt % NSTG;
        if (kt + 1 < NKT) { CP_WAIT(1); } else { CP_WAIT(0); }
        __syncthreads();
        if (kt + 2 < NKT) {
            issue_stage(kt + 2, (kt + 2) % NSTG);
            CP_COMMIT();
        }

        const uint32_t sb = sbase + (uint32_t)s * STG_B;
        const uint32_t aP = sb + a_off;
        const uint32_t bP = sb + TILE_A + b_off;

#pragma unroll
        for (int kk = 0; kk < 2; kk++) {
            const uint32_t ko = kk * 32;
            uint32_t ar[2][4], br[NP][4];
#pragma unroll
            for (int mt = 0; mt < 2; mt++)
                ldsm4(ar[mt], aP + mt * (16 * KSB) + ko);
#pragma unroll
            for (int p = 0; p < NP; p++)
                ldsm4(br[p], bP + p * (16 * KSB) + ko);
#pragma unroll
            for (int mt = 0; mt < 2; mt++)
#pragma unroll
                for (int nt = 0; nt < NTW; nt++) {
                    const int p = nt >> 1, o = (nt & 1) * 2;
                    mma_f16(acc[mt][nt], ar[mt], br[p][o], br[p][o + 1]);
                }
        }
    }

    // ---------------- epilogue ----------------------------------------------
    const int gr_base = gm0 + m0 + (l >> 2);
    const int gc_loc  = 2 * (l & 3);

    if (MODE == 0) {
        const int which    = gn0 / C_;             // 256 | C_ boundaries align
        const int rem_base = gn0 - which * C_;
        __half* dst = (which == 0) ? g_q : (which == 1) ? g_k : g_v;
        const float sc = (which == 0) ? 0.125f : 1.0f;
#pragma unroll
        for (int mt = 0; mt < 2; mt++)
#pragma unroll
            for (int nt = 0; nt < NTW; nt++) {
                const float* c = acc[mt][nt];
                const int gcn = n0 + nt * 8 + gc_loc;
                const int gc  = gn0 + gcn;
                float2 bb = *(const float2*)&bias[gc];
                const int rem = rem_base + gcn;
                const int h = rem >> 6, d = rem & 63;
#pragma unroll
                for (int hf = 0; hf < 2; hf++) {
                    const int gr = gr_base + mt * 16 + hf * 8;
                    const int b  = gr >> 10, tq = gr & 1023;
                    size_t idx = (((size_t)(b * H_ + h)) * T_ + tq) * D_ + d;
                    *(uint32_t*)&dst[idx] = pack_h2((c[hf * 2 + 0] + bb.x) * sc,
                                                    (c[hf * 2 + 1] + bb.y) * sc);
                }
            }
    } else {
#pragma unroll
        for (int mt = 0; mt < 2; mt++)
#pragma unroll
            for (int nt = 0; nt < NTW; nt++) {
                const float* c = acc[mt][nt];
                const int gc = gn0 + n0 + nt * 8 + gc_loc;
                float2 bb = *(const float2*)&bias[gc];
#pragma unroll
                for (int hf = 0; hf < 2; hf++) {
                    const int gr = gr_base + mt * 16 + hf * 8;
                    float2 o;
                    o.x = c[hf * 2 + 0] + bb.x;
                    o.y = c[hf * 2 + 1] + bb.y;
                    *(float2*)&out[(size_t)gr * C_ + gc] = o;
                }
            }
    }
}

#define GEMM_SMEM0 (NSTG * (TILE_A + 256 * KSB))  /* 92160 */
#define GEMM_SMEM1 (NSTG * (TILE_A + 128 * KSB))  /* 61440 */

// ---------------- tensor-core flash attention (fp16 single) -----------------
// CTA: 128 q-rows x (b,h). 8 warps x 16 rows. 64-key tiles, 16 iters.
#define NT_  16
#define ROWB 144
#define SQ    0                       /* 18432 */
#define SK(s) (18432 + (s) * 9216)
#define SV(s) (36864 + (s) * 9216)
#define SP    55296                   /* 18432 */
#define ATTN_SMEM 73728

__global__ __launch_bounds__(256, 1) void attn_mma_kernel()
{
    extern __shared__ char smem[];
    const uint32_t sbase = smem_u32(smem);
    const int tid = threadIdx.x, wid = tid >> 5, l = tid & 31;
    const int bh = blockIdx.y, q0 = blockIdx.x * 128;
    const size_t hb = (size_t)bh * T_ * D_;
    const __half *Qg = g_q + hb, *Kg = g_k + hb, *Vg = g_v + hb;

    const int m0 = wid * 16;
    const int lq = l >> 3, lr = l & 7;
    const uint32_t a_off = (uint32_t)((m0 + (lq & 1) * 8 + lr) * ROWB + (lq >> 1) * 16);
    const uint32_t b_off = (uint32_t)(((lq >> 1) * 8 + lr) * ROWB + (lq & 1) * 16);
    const uint32_t v_off = (uint32_t)(((lq & 1) * 8 + lr) * ROWB + (lq >> 1) * 16);

#pragma unroll
    for (int it = 0; it < 4; it++) {
        int c = it * 256 + tid;
        int row = c >> 3, ch = c & 7;
        CP_ASYNC16(sbase + SQ + row * ROWB + ch * 16,
                   Qg + (size_t)(q0 + row) * D_ + ch * 8);
    }
    auto load_kv = [&](int kt, int s) {
        const int r0 = kt * 64;
#pragma unroll
        for (int a = 0; a < 2; a++) {
            const __half* src = a ? Vg : Kg;
            const uint32_t dst = sbase + (a ? SV(s) : SK(s));
#pragma unroll
            for (int it = 0; it < 2; it++) {
                int c = it * 256 + tid;
                int row = c >> 3, ch = c & 7;
                CP_ASYNC16(dst + row * ROWB + ch * 16,
                           src + (size_t)(r0 + row) * D_ + ch * 8);
            }
        }
    };
    load_kv(0, 0);
    CP_COMMIT();
    CP_WAIT(0);
    __syncthreads();

    uint32_t qf[4][4];
#pragma unroll
    for (int kk = 0; kk < 4; kk++)
        ldsm4(qf[kk], sbase + SQ + a_off + kk * 32);

    float mrow[2] = {-1e30f, -1e30f}, lsum[2] = {0.f, 0.f};
    float acc[8][4];
#pragma unroll
    for (int nt = 0; nt < 8; nt++)
#pragma unroll
        for (int j = 0; j < 4; j++) acc[nt][j] = 0.f;

    const uint32_t prow0 = (uint32_t)((m0 + (l >> 2)) * ROWB + (l & 3) * 4);

    for (int kt = 0; kt < NT_; kt++) {
        const int s = kt & 1;
        __syncthreads();
        if (kt + 1 < NT_) {
            load_kv(kt + 1, s ^ 1);
            CP_COMMIT();
            CP_WAIT(1);
        } else {
            CP_WAIT(0);
        }
        __syncthreads();

        float sc[8][4];
#pragma unroll
        for (int nt = 0; nt < 8; nt++)
#pragma unroll
            for (int j = 0; j < 4; j++) sc[nt][j] = 0.f;

        const uint32_t kb = sbase + SK(s) + b_off;
#pragma unroll
        for (int kk = 0; kk < 4; kk++) {
            uint32_t b4[4][4];
#pragma unroll
            for (int p = 0; p < 4; p++)
                ldsm4(b4[p], kb + p * (16 * ROWB) + kk * 32);
#pragma unroll
            for (int nt = 0; nt < 8; nt++) {
                const int p = nt >> 1, o = (nt & 1) * 2;
                mma_f16(sc[nt], qf[kk], b4[p][o], b4[p][o + 1]);
            }
        }

        float mx0 = sc[0][0], mx1 = sc[0][2];
#pragma unroll
        for (int nt = 0; nt < 8; nt++) {
            mx0 = fmaxf(mx0, fmaxf(sc[nt][0], sc[nt][1]));
            mx1 = fmaxf(mx1, fmaxf(sc[nt][2], sc[nt][3]));
        }
        mx0 = fmaxf(mx0, __shfl_xor_sync(0xffffffffu, mx0, 1));
        mx0 = fmaxf(mx0, __shfl_xor_sync(0xffffffffu, mx0, 2));
        mx1 = fmaxf(mx1, __shfl_xor_sync(0xffffffffu, mx1, 1));
        mx1 = fmaxf(mx1, __shfl_xor_sync(0xffffffffu, mx1, 2));
        const float mn0 = fmaxf(mrow[0], mx0);
        const float mn1 = fmaxf(mrow[1], mx1);
        const float f0 = __expf(mrow[0] - mn0);
        const float f1 = __expf(mrow[1] - mn1);
        mrow[0] = mn0; mrow[1] = mn1;

        float rs0 = 0.f, rs1 = 0.f;
#pragma unroll
        for (int nt = 0; nt < 8; nt++) {
            float p0 = __expf(sc[nt][0] - mn0);
            float p1 = __expf(sc[nt][1] - mn0);
            float p2 = __expf(sc[nt][2] - mn1);
            float p3 = __expf(sc[nt][3] - mn1);
            rs0 += p0 + p1; rs1 += p2 + p3;
            const uint32_t o0 = prow0 + nt * 16;
            *(uint32_t*)(smem + SP + o0) = pack_h2(p0, p1);
            *(uint32_t*)(smem + SP + o0 + 8 * ROWB) = pack_h2(p2, p3);
            acc[nt][0] *= f0; acc[nt][1] *= f0;
            acc[nt][2] *= f1; acc[nt][3] *= f1;
        }
        rs0 += __shfl_xor_sync(0xffffffffu, rs0, 1);
        rs0 += __shfl_xor_sync(0xffffffffu, rs0, 2);
        rs1 += __shfl_xor_sync(0xffffffffu, rs1, 1);
        rs1 += __shfl_xor_sync(0xffffffffu, rs1, 2);
        lsum[0] = lsum[0] * f0 + rs0;
        lsum[1] = lsum[1] * f1 + rs1;
        __syncwarp();

        const uint32_t pb = sbase + SP + a_off;
        const uint32_t vb = sbase + SV(s) + v_off;
#pragma unroll
        for (int kk = 0; kk < 4; kk++) {
            uint32_t pf[4];
            ldsm4(pf, pb + kk * 32);
            uint32_t v4[4][4];
#pragma unroll
            for (int p = 0; p < 4; p++)
                ldsm4t(v4[p], vb + kk * (16 * ROWB) + p * 32);
#pragma unroll
            for (int nt = 0; nt < 8; nt++) {
                const int p = nt >> 1, o = (nt & 1) * 2;
                mma_f16(acc[nt], pf, v4[p][o], v4[p][o + 1]);
            }
        }
    }

    const int b = bh / H_, h = bh - b * H_;
    const float i0 = 1.f / lsum[0];
    const float i1 = 1.f / lsum[1];
    const int r0 = q0 + m0 + (l >> 2);
    const size_t base0 = ((size_t)b * T_ + r0) * C_ + h * D_ + 2 * (l & 3);
    const size_t base1 = base0 + 8 * (size_t)C_;
#pragma unroll
    for (int nt = 0; nt < 8; nt++) {
        *(uint32_t*)&g_c[base0 + nt * 8] = pack_h2(acc[nt][0] * i0, acc[nt][1] * i0);
        *(uint32_t*)&g_c[base1 + nt * 8] = pack_h2(acc[nt][2] * i1, acc[nt][3] * i1);
    }
}

// ---------------------------------------------------------------------------
extern "C" void kernel_launch(void* const* d_in, const int* in_sizes, int n_in,
                              void* d_out, int out_size)
{
    const float* hidden = (const float*)d_in[0];
    const float* qkv_w  = (const float*)d_in[1];
    const float* qkv_b  = (const float*)d_in[2];
    const float* proj_w = (const float*)d_in[3];
    const float* proj_b = (const float*)d_in[4];
    float* out = (float*)d_out;
    (void)in_sizes; (void)n_in; (void)out_size;

    cudaFuncSetAttribute(gemm_mma_kernel<0>,
                         cudaFuncAttributeMaxDynamicSharedMemorySize, GEMM_SMEM0);
    cudaFuncSetAttribute(gemm_mma_kernel<1>,
                         cudaFuncAttributeMaxDynamicSharedMemorySize, GEMM_SMEM1);
    cudaFuncSetAttribute(attn_mma_kernel,
                         cudaFuncAttributeMaxDynamicSharedMemorySize, ATTN_SMEM);

    // 0) operand conversions
    conv_h_kernel<<<(M_ * C_) / 256, 256>>>(hidden, M_ * C_);
    conv_transpose_kernel<<<dim3(N1_ / 32, C_ / 32), dim3(32, 8)>>>(qkv_w, 0, C_, N1_);
    conv_transpose_kernel<<<dim3(C_ / 32, C_ / 32), dim3(32, 8)>>>(proj_w, 1, C_, C_);

    // 1) QKV projection (128x256 CTAs) -> Q (pre-scaled) / K / V fp16
    gemm_mma_kernel<0><<<dim3(N1_ / 256, M_ / 128), 512, GEMM_SMEM0>>>(qkv_b, nullptr);

    // 2) attention -> ctx fp16
    attn_mma_kernel<<<dim3(T_ / 128, B_ * H_), 256, ATTN_SMEM>>>();

    // 3) output projection (128x128 CTAs) -> out fp32
    gemm_mma_kernel<1><<<dim3(C_ / 128, M_ / 128), 512, GEMM_SMEM1>>>(proj_b, out);
}

// round 13
// speedup vs baseline: 6.1371x; 1.1990x over previous
#include <cuda_runtime.h>
#include <cuda_fp16.h>
#include <cstdint>
#include <cstddef>

#define B_   8
#define T_   1024
#define C_   768
#define H_   12
#define D_   64
#define M_   (B_ * T_)     /* 8192 */
#define N1_  (3 * C_)      /* 2304 */

// ---------------- device-global scratch (all fp16 single) -------------------
__device__ __half g_a [(size_t)M_ * C_];     // hidden
__device__ __half g_c [(size_t)M_ * C_];     // ctx
__device__ __half g_wq[(size_t)N1_ * C_];    // qkv_w^T [2304,768]
__device__ __half g_wp[(size_t)C_ * C_];     // proj_w^T [768,768]
__device__ __half g_q [(size_t)M_ * C_];     // [B*H,T,D], pre-scaled 0.125
__device__ __half g_k [(size_t)M_ * C_];
__device__ __half g_v [(size_t)M_ * C_];

// ---------------- PTX helpers ----------------------------------------------
__device__ __forceinline__ uint32_t smem_u32(const void* p) {
    uint32_t a;
    asm("{ .reg .u64 t; cvta.to.shared.u64 t, %1; cvt.u32.u64 %0, t; }"
        : "=r"(a) : "l"(p));
    return a;
}

#define CP_ASYNC16(dst, src) \
    asm volatile("cp.async.cg.shared.global [%0], [%1], 16;" \
                 :: "r"(dst), "l"(src) : "memory")
#define CP_COMMIT() asm volatile("cp.async.commit_group;" ::: "memory")
#define CP_WAIT(n)  asm volatile("cp.async.wait_group %0;" :: "n"(n) : "memory")

__device__ __forceinline__ void ldsm4(uint32_t* r, uint32_t a) {
    asm volatile("ldmatrix.sync.aligned.m8n8.x4.shared.b16 {%0,%1,%2,%3}, [%4];"
                 : "=r"(r[0]), "=r"(r[1]), "=r"(r[2]), "=r"(r[3]) : "r"(a));
}
__device__ __forceinline__ void ldsm4t(uint32_t* r, uint32_t a) {
    asm volatile("ldmatrix.sync.aligned.m8n8.x4.trans.shared.b16 {%0,%1,%2,%3}, [%4];"
                 : "=r"(r[0]), "=r"(r[1]), "=r"(r[2]), "=r"(r[3]) : "r"(a));
}

__device__ __forceinline__ void mma_f16(float* c, const uint32_t* a,
                                        uint32_t b0, uint32_t b1) {
    asm volatile(
        "mma.sync.aligned.m16n8k16.row.col.f32.f16.f16.f32 "
        "{%0,%1,%2,%3}, {%4,%5,%6,%7}, {%8,%9}, {%0,%1,%2,%3};"
        : "+f"(c[0]), "+f"(c[1]), "+f"(c[2]), "+f"(c[3])
        : "r"(a[0]), "r"(a[1]), "r"(a[2]), "r"(a[3]), "r"(b0), "r"(b1));
}

__device__ __forceinline__ uint32_t pack_h2(float x, float y) {
    __half2 h = __halves2half2(__float2half_rn(x), __float2half_rn(y));
    return *(uint32_t*)&h;
}

// ---------------- conversion kernels ----------------------------------------
__global__ void conv_h_kernel(const float* __restrict__ src, int n)
{
    int i = blockIdx.x * blockDim.x + threadIdx.x;
    if (i >= n) return;
    g_a[i] = __float2half_rn(src[i]);
}

// W [K, N] fp32 -> W^T [N, K] fp16. sel 0: qkv_w, 1: proj_w
__global__ void conv_transpose_kernel(const float* __restrict__ src, int dst_sel,
                                      int K, int N)
{
    __shared__ float tile[32][33];
    int kx = blockIdx.y * 32;
    int nx = blockIdx.x * 32;
    int tx = threadIdx.x;
    int ty = threadIdx.y;
    for (int i = ty; i < 32; i += 8)
        tile[i][tx] = src[(size_t)(kx + i) * N + nx + tx];
    __syncthreads();
    __half* dst = dst_sel ? g_wp : g_wq;
    for (int i = ty; i < 32; i += 8)
        dst[(size_t)(nx + i) * K + kx + tx] = __float2half_rn(tile[tx][i]);
}

// ---------------- mma.sync fp16 GEMM ----------------------------------------
// Both modes: CTA 128x128, 256 thr, 8 warps 4x2, warp 32x64, 3-stage.
// 2 CTAs/SM so barrier drains in one CTA are hidden by the other.
#define BKE 32
#define KSB 80
#define TILE_A (128 * KSB)           /* 10240 */
#define NSTG 3
#define NKT 24
#define STG_B (2 * TILE_A)
#define GEMM_SMEM (NSTG * STG_B)     /* 61440 */

template <int MODE>
__global__ __launch_bounds__(256, 2)
void gemm_mma_kernel(const float* __restrict__ bias, float* __restrict__ out)
{
    extern __shared__ char smem[];
    const uint32_t sbase = smem_u32(smem);
    const int tid = threadIdx.x;
    const int wid = tid >> 5;          // 0..7
    const int l   = tid & 31;
    const int gm0 = blockIdx.y * 128;
    const int gn0 = blockIdx.x * 128;

    const __half* gA = MODE ? g_c  : g_a;
    const __half* gB = MODE ? g_wp : g_wq;

    const int m0 = (wid & 3) * 32;
    const int n0 = (wid >> 2) * 64;

    const int lq = l >> 3, lr = l & 7;
    const uint32_t a_off = (uint32_t)((m0 + (lq & 1) * 8 + lr) * KSB + ((lq >> 1) * 8) * 2);
    const uint32_t b_off = (uint32_t)((n0 + (lq >> 1) * 8 + lr) * KSB + ((lq & 1) * 8) * 2);

    float acc[2][8][4];
#pragma unroll
    for (int mt = 0; mt < 2; mt++)
#pragma unroll
        for (int nt = 0; nt < 8; nt++)
#pragma unroll
            for (int j = 0; j < 4; j++) acc[mt][nt][j] = 0.f;

    auto issue_stage = [&](int kt, int s) {
        const int k0 = kt * BKE;
        const uint32_t sb = sbase + (uint32_t)s * STG_B;
#pragma unroll
        for (int i = 0; i < 4; i++) {
            const int c = i * 256 + tid;          // 0..1023
            const int row = c >> 2, ch = c & 3;
            const __half* src = (row < 128) ? gA : gB;
            const int grow = (row < 128) ? (gm0 + row) : (gn0 + row - 128);
            CP_ASYNC16(sb + (uint32_t)row * KSB + ch * 16,
                       src + (size_t)grow * C_ + k0 + ch * 8);
        }
    };

    issue_stage(0, 0); CP_COMMIT();
    issue_stage(1, 1); CP_COMMIT();

#pragma unroll 1
    for (int kt = 0; kt < NKT; kt++) {
        const int s = kt % NSTG;
        if (kt + 1 < NKT) { CP_WAIT(1); } else { CP_WAIT(0); }
        __syncthreads();
        if (kt + 2 < NKT) {
            issue_stage(kt + 2, (kt + 2) % NSTG);
            CP_COMMIT();
        }

        const uint32_t aP = sbase + (uint32_t)s * STG_B + a_off;
        const uint32_t bP = sbase + (uint32_t)s * STG_B + TILE_A + b_off;

#pragma unroll
        for (int kk = 0; kk < 2; kk++) {
            const uint32_t ko = kk * 32;
            uint32_t ar[2][4], br[4][4];
#pragma unroll
            for (int mt = 0; mt < 2; mt++)
                ldsm4(ar[mt], aP + mt * (16 * KSB) + ko);
#pragma unroll
            for (int p = 0; p < 4; p++)
                ldsm4(br[p], bP + p * (16 * KSB) + ko);
#pragma unroll
            for (int mt = 0; mt < 2; mt++)
#pragma unroll
                for (int nt = 0; nt < 8; nt++) {
                    const int p = nt >> 1, o = (nt & 1) * 2;
                    mma_f16(acc[mt][nt], ar[mt], br[p][o], br[p][o + 1]);
                }
        }
    }

    // ---------------- epilogue ----------------------------------------------
    const int gr_base = gm0 + m0 + (l >> 2);
    const int gc_loc  = 2 * (l & 3);

    if (MODE == 0) {
        const int which    = gn0 / C_;          // 128 | 768 boundaries align
        const int rem_base = gn0 - which * C_;
        __half* dst = (which == 0) ? g_q : (which == 1) ? g_k : g_v;
        const float sc = (which == 0) ? 0.125f : 1.0f;
#pragma unroll
        for (int mt = 0; mt < 2; mt++)
#pragma unroll
            for (int nt = 0; nt < 8; nt++) {
                const float* c = acc[mt][nt];
                const int gcn = n0 + nt * 8 + gc_loc;
                const int gc  = gn0 + gcn;
                float2 bb = *(const float2*)&bias[gc];
                const int rem = rem_base + gcn;
                const int h = rem >> 6, d = rem & 63;
#pragma unroll
                for (int hf = 0; hf < 2; hf++) {
                    const int gr = gr_base + mt * 16 + hf * 8;
                    const int b  = gr >> 10, tq = gr & 1023;
                    size_t idx = (((size_t)(b * H_ + h)) * T_ + tq) * D_ + d;
                    *(uint32_t*)&dst[idx] = pack_h2((c[hf * 2 + 0] + bb.x) * sc,
                                                    (c[hf * 2 + 1] + bb.y) * sc);
                }
            }
    } else {
#pragma unroll
        for (int mt = 0; mt < 2; mt++)
#pragma unroll
            for (int nt = 0; nt < 8; nt++) {
                const float* c = acc[mt][nt];
                const int gc = gn0 + n0 + nt * 8 + gc_loc;
                float2 bb = *(const float2*)&bias[gc];
#pragma unroll
                for (int hf = 0; hf < 2; hf++) {
                    const int gr = gr_base + mt * 16 + hf * 8;
                    float2 o;
                    o.x = c[hf * 2 + 0] + bb.x;
                    o.y = c[hf * 2 + 1] + bb.y;
                    *(float2*)&out[(size_t)gr * C_ + gc] = o;
                }
            }
    }
}

// ---------------- tensor-core flash attention (fp16, register P) ------------
// CTA: 128 q-rows x (b,h). 8 warps x 16 rows. 64-key tiles, 16 iters.
// P stays in registers: S-accumulator fragments ARE the PV A-operand
// fragments (c0,c1 -> a0 ; c2,c3 -> a1 ; next nt -> a2,a3).
#define NT_  16
#define ROWB 144
#define SQ    0                       /* 18432 */
#define SK(s) (18432 + (s) * 9216)
#define SV(s) (36864 + (s) * 9216)
#define ATTN_SMEM 55296

__global__ __launch_bounds__(256, 2) void attn_mma_kernel()
{
    extern __shared__ char smem[];
    const uint32_t sbase = smem_u32(smem);
    const int tid = threadIdx.x, wid = tid >> 5, l = tid & 31;
    const int bh = blockIdx.y, q0 = blockIdx.x * 128;
    const size_t hb = (size_t)bh * T_ * D_;
    const __half *Qg = g_q + hb, *Kg = g_k + hb, *Vg = g_v + hb;

    const int m0 = wid * 16;
    const int lq = l >> 3, lr = l & 7;
    const uint32_t a_off = (uint32_t)((m0 + (lq & 1) * 8 + lr) * ROWB + (lq >> 1) * 16);
    const uint32_t b_off = (uint32_t)(((lq >> 1) * 8 + lr) * ROWB + (lq & 1) * 16);
    const uint32_t v_off = (uint32_t)(((lq & 1) * 8 + lr) * ROWB + (lq >> 1) * 16);

#pragma unroll
    for (int it = 0; it < 4; it++) {
        int c = it * 256 + tid;
        int row = c >> 3, ch = c & 7;
        CP_ASYNC16(sbase + SQ + row * ROWB + ch * 16,
                   Qg + (size_t)(q0 + row) * D_ + ch * 8);
    }
    auto load_kv = [&](int kt, int s) {
        const int r0 = kt * 64;
#pragma unroll
        for (int a = 0; a < 2; a++) {
            const __half* src = a ? Vg : Kg;
            const uint32_t dst = sbase + (a ? SV(s) : SK(s));
#pragma unroll
            for (int it = 0; it < 2; it++) {
                int c = it * 256 + tid;
                int row = c >> 3, ch = c & 7;
                CP_ASYNC16(dst + row * ROWB + ch * 16,
                           src + (size_t)(r0 + row) * D_ + ch * 8);
            }
        }
    };
    load_kv(0, 0);
    CP_COMMIT();
    CP_WAIT(0);
    __syncthreads();

    uint32_t qf[4][4];
#pragma unroll
    for (int kk = 0; kk < 4; kk++)
        ldsm4(qf[kk], sbase + SQ + a_off + kk * 32);

    float mrow[2] = {-1e30f, -1e30f}, lsum[2] = {0.f, 0.f};
    float acc[8][4];
#pragma unroll
    for (int nt = 0; nt < 8; nt++)
#pragma unroll
        for (int j = 0; j < 4; j++) acc[nt][j] = 0.f;

    for (int kt = 0; kt < NT_; kt++) {
        const int s = kt & 1;
        __syncthreads();
        if (kt + 1 < NT_) {
            load_kv(kt + 1, s ^ 1);
            CP_COMMIT();
            CP_WAIT(1);
        } else {
            CP_WAIT(0);
        }
        __syncthreads();

        // ---- S = Q K^T ----
        float sc[8][4];
#pragma unroll
        for (int nt = 0; nt < 8; nt++)
#pragma unroll
            for (int j = 0; j < 4; j++) sc[nt][j] = 0.f;

        const uint32_t kb = sbase + SK(s) + b_off;
#pragma unroll
        for (int kk = 0; kk < 4; kk++) {
            uint32_t b4[4][4];
#pragma unroll
            for (int p = 0; p < 4; p++)
                ldsm4(b4[p], kb + p * (16 * ROWB) + kk * 32);
#pragma unroll
            for (int nt = 0; nt < 8; nt++) {
                const int p = nt >> 1, o = (nt & 1) * 2;
                mma_f16(sc[nt], qf[kk], b4[p][o], b4[p][o + 1]);
            }
        }

        // ---- online softmax (p values kept in sc registers) ----
        float mx0 = sc[0][0], mx1 = sc[0][2];
#pragma unroll
        for (int nt = 0; nt < 8; nt++) {
            mx0 = fmaxf(mx0, fmaxf(sc[nt][0], sc[nt][1]));
            mx1 = fmaxf(mx1, fmaxf(sc[nt][2], sc[nt][3]));
        }
        mx0 = fmaxf(mx0, __shfl_xor_sync(0xffffffffu, mx0, 1));
        mx0 = fmaxf(mx0, __shfl_xor_sync(0xffffffffu, mx0, 2));
        mx1 = fmaxf(mx1, __shfl_xor_sync(0xffffffffu, mx1, 1));
        mx1 = fmaxf(mx1, __shfl_xor_sync(0xffffffffu, mx1, 2));
        const float mn0 = fmaxf(mrow[0], mx0);
        const float mn1 = fmaxf(mrow[1], mx1);
        const float f0 = __expf(mrow[0] - mn0);
        const float f1 = __expf(mrow[1] - mn1);
        mrow[0] = mn0; mrow[1] = mn1;

        float rs0 = 0.f, rs1 = 0.f;
#pragma unroll
        for (int nt = 0; nt < 8; nt++) {
            float p0 = __expf(sc[nt][0] - mn0);
            float p1 = __expf(sc[nt][1] - mn0);
            float p2 = __expf(sc[nt][2] - mn1);
            float p3 = __expf(sc[nt][3] - mn1);
            rs0 += p0 + p1; rs1 += p2 + p3;
            sc[nt][0] = p0; sc[nt][1] = p1; sc[nt][2] = p2; sc[nt][3] = p3;
            acc[nt][0] *= f0; acc[nt][1] *= f0;
            acc[nt][2] *= f1; acc[nt][3] *= f1;
        }
        rs0 += __shfl_xor_sync(0xffffffffu, rs0, 1);
        rs0 += __shfl_xor_sync(0xffffffffu, rs0, 2);
        rs1 += __shfl_xor_sync(0xffffffffu, rs1, 1);
        rs1 += __shfl_xor_sync(0xffffffffu, rs1, 2);
        lsum[0] = lsum[0] * f0 + rs0;
        lsum[1] = lsum[1] * f1 + rs1;

        // ---- O += P V, P fragments built in registers ----
        const uint32_t vb = sbase + SV(s) + v_off;
#pragma unroll
        for (int kk = 0; kk < 4; kk++) {
            uint32_t pf[4];
            pf[0] = pack_h2(sc[2 * kk][0],     sc[2 * kk][1]);
            pf[1] = pack_h2(sc[2 * kk][2],     sc[2 * kk][3]);
            pf[2] = pack_h2(sc[2 * kk + 1][0], sc[2 * kk + 1][1]);
            pf[3] = pack_h2(sc[2 * kk + 1][2], sc[2 * kk + 1][3]);
            uint32_t v4[4][4];
#pragma unroll
            for (int p = 0; p < 4; p++)
                ldsm4t(v4[p], vb + kk * (16 * ROWB) + p * 32);
#pragma unroll
            for (int nt = 0; nt < 8; nt++) {
                const int p = nt >> 1, o = (nt & 1) * 2;
                mma_f16(acc[nt], pf, v4[p][o], v4[p][o + 1]);
            }
        }
    }

    // ---- epilogue: ctx -> fp16 [B*T, C] ----
    const int b = bh / H_, h = bh - b * H_;
    const float i0 = 1.f / lsum[0];
    const float i1 = 1.f / lsum[1];
    const int r0 = q0 + m0 + (l >> 2);
    const size_t base0 = ((size_t)b * T_ + r0) * C_ + h * D_ + 2 * (l & 3);
    const size_t base1 = base0 + 8 * (size_t)C_;
#pragma unroll
    for (int nt = 0; nt < 8; nt++) {
        *(uint32_t*)&g_c[base0 + nt * 8] = pack_h2(acc[nt][0] * i0, acc[nt][1] * i0);
        *(uint32_t*)&g_c[base1 + nt * 8] = pack_h2(acc[nt][2] * i1, acc[nt][3] * i1);
    }
}

// ---------------------------------------------------------------------------
extern "C" void kernel_launch(void* const* d_in, const int* in_sizes, int n_in,
                              void* d_out, int out_size)
{
    const float* hidden = (const float*)d_in[0];
    const float* qkv_w  = (const float*)d_in[1];
    const float* qkv_b  = (const float*)d_in[2];
    const float* proj_w = (const float*)d_in[3];
    const float* proj_b = (const float*)d_in[4];
    float* out = (float*)d_out;
    (void)in_sizes; (void)n_in; (void)out_size;

    cudaFuncSetAttribute(gemm_mma_kernel<0>,
                         cudaFuncAttributeMaxDynamicSharedMemorySize, GEMM_SMEM);
    cudaFuncSetAttribute(gemm_mma_kernel<1>,
                         cudaFuncAttributeMaxDynamicSharedMemorySize, GEMM_SMEM);
    cudaFuncSetAttribute(attn_mma_kernel,
                         cudaFuncAttributeMaxDynamicSharedMemorySize, ATTN_SMEM);

    // 0) operand conversions
    conv_h_kernel<<<(M_ * C_) / 256, 256>>>(hidden, M_ * C_);
    conv_transpose_kernel<<<dim3(N1_ / 32, C_ / 32), dim3(32, 8)>>>(qkv_w, 0, C_, N1_);
    conv_transpose_kernel<<<dim3(C_ / 32, C_ / 32), dim3(32, 8)>>>(proj_w, 1, C_, C_);

    // 1) QKV projection -> Q (pre-scaled) / K / V fp16
    gemm_mma_kernel<0><<<dim3(N1_ / 128, M_ / 128), 256, GEMM_SMEM>>>(qkv_b, nullptr);

    // 2) attention -> ctx fp16
    attn_mma_kernel<<<dim3(T_ / 128, B_ * H_), 256, ATTN_SMEM>>>();

    // 3) output projection -> out fp32
    gemm_mma_kernel<1><<<dim3(C_ / 128, M_ / 128), 256, GEMM_SMEM>>>(proj_b, out);
}